// round 1
// baseline (speedup 1.0000x reference)
#include <cuda_runtime.h>

#define SEQ  4096
#define DIM  1024
#define NH   16
#define HD   64

// Scratch (allocation-free rule: __device__ globals)
__device__ float g_q[(size_t)NH * SEQ * HD];
__device__ float g_k[(size_t)NH * SEQ * HD];
__device__ float g_v[(size_t)NH * SEQ * HD];
__device__ float g_att[(size_t)SEQ * DIM];

// ---------------------------------------------------------------------------
// SGEMM: C[M,N] = A[M,K] * B[K,N] + bias, K = 1024.
// MODE 0: A = param (x), epilogue scatters into g_q/g_k/g_v as [H,SEQ,HD].
// MODE 1: A = g_att, epilogue writes C (d_out) plainly.
// Tile 128x128x16, 256 threads, 8x8 per-thread microtile.
// ---------------------------------------------------------------------------
template <int N_, int MODE>
__global__ __launch_bounds__(256) void sgemm_k(const float* __restrict__ A_in,
                                               const float* __restrict__ B,
                                               const float* __restrict__ bias,
                                               float* __restrict__ C) {
    const int K = DIM;
    const float* A = (MODE == 1) ? g_att : A_in;

    __shared__ float As[16][128];
    __shared__ float Bs[16][128];

    const int t  = threadIdx.x;
    const int tx = t & 15;
    const int ty = t >> 4;
    const int rowBase = blockIdx.y * 128;
    const int colBase = blockIdx.x * 128;

    float acc[8][8];
#pragma unroll
    for (int i = 0; i < 8; i++)
#pragma unroll
        for (int j = 0; j < 8; j++) acc[i][j] = 0.f;

    for (int k0 = 0; k0 < K; k0 += 16) {
#pragma unroll
        for (int i = 0; i < 2; i++) {
            int id = t + i * 256;          // 0..511
            int r  = id >> 2;              // 0..127
            int kk = (id & 3) << 2;        // 0,4,8,12
            float4 v = *(const float4*)&A[(size_t)(rowBase + r) * K + k0 + kk];
            As[kk + 0][r] = v.x; As[kk + 1][r] = v.y;
            As[kk + 2][r] = v.z; As[kk + 3][r] = v.w;
        }
#pragma unroll
        for (int i = 0; i < 2; i++) {
            int id = t + i * 256;
            int r  = id >> 5;              // 0..15
            int c  = (id & 31) << 2;       // 0..124
            *(float4*)&Bs[r][c] = *(const float4*)&B[(size_t)(k0 + r) * N_ + colBase + c];
        }
        __syncthreads();

#pragma unroll
        for (int kk = 0; kk < 16; kk++) {
            float a[8], b[8];
            *(float4*)&a[0] = *(const float4*)&As[kk][ty * 8];
            *(float4*)&a[4] = *(const float4*)&As[kk][ty * 8 + 4];
            *(float4*)&b[0] = *(const float4*)&Bs[kk][tx * 8];
            *(float4*)&b[4] = *(const float4*)&Bs[kk][tx * 8 + 4];
#pragma unroll
            for (int i = 0; i < 8; i++)
#pragma unroll
                for (int j = 0; j < 8; j++) acc[i][j] += a[i] * b[j];
        }
        __syncthreads();
    }

#pragma unroll
    for (int i = 0; i < 8; i++) {
        int r = rowBase + ty * 8 + i;
#pragma unroll
        for (int j = 0; j < 8; j++) {
            int cg = colBase + tx * 8 + j;
            float v = acc[i][j] + bias[cg];
            if (MODE == 0) {
                int which = cg >> 10;      // 0=q 1=k 2=v
                int c2    = cg & 1023;
                int head  = c2 >> 6;
                int d     = c2 & 63;
                float* dst = (which == 0) ? g_q : (which == 1) ? g_k : g_v;
                dst[((size_t)head * SEQ + r) * HD + d] = v;
            } else {
                C[(size_t)r * N_ + cg] = v;
            }
        }
    }
}

// ---------------------------------------------------------------------------
// Flash attention: one block per (64-query tile, head). 256 threads.
// Qs: [64][64] plain. KVs: [64][64] XOR-swizzled (rows of K then V).
// Ss: [64][68] padded score/prob tile. Online softmax, fp32 O in registers.
// ---------------------------------------------------------------------------
__device__ __forceinline__ int kvidx(int r, int c4) {
    return r * 64 + ((c4 ^ (r & 15)) << 2);
}

__global__ __launch_bounds__(256) void attn_kernel() {
    extern __shared__ float sm[];
    float* Qs  = sm;             // 4096 floats
    float* KVs = sm + 4096;      // 4096 floats (swizzled)
    float* Ss  = sm + 8192;      // 64*68 floats

    const int t  = threadIdx.x;
    const int h  = blockIdx.y;
    const int qt = blockIdx.x;

    const float* Qg = g_q + ((size_t)h * SEQ + qt * 64) * HD;
    const float* Kg = g_k + (size_t)h * SEQ * HD;
    const float* Vg = g_v + (size_t)h * SEQ * HD;

    // Load Q tile (64x64)
#pragma unroll
    for (int i = 0; i < 4; i++) {
        int id = t + i * 256;
        int r  = id >> 4;
        int c  = (id & 15) << 2;
        *(float4*)&Qs[r * 64 + c] = *(const float4*)&Qg[r * 64 + c];
    }

    const int orow = t >> 2;   // 0..63  (softmax / O-accum row)
    const int og   = t & 3;    // column group of 16
    const int str  = t >> 4;   // 0..15  (S-phase 4-row group)
    const int stc  = t & 15;   // 0..15  (S-phase 4-col group)

    float o[16];
#pragma unroll
    for (int i = 0; i < 16; i++) o[i] = 0.f;
    float m = -1e30f, l = 0.f;

    for (int kt = 0; kt < SEQ / 64; kt++) {
        __syncthreads();   // prior PV done reading KVs / Ss
        const float* Kt = Kg + (size_t)kt * 64 * HD;
#pragma unroll
        for (int i = 0; i < 4; i++) {
            int id = t + i * 256;
            int r  = id >> 4;
            int c4 = id & 15;
            *(float4*)&KVs[kvidx(r, c4)] = *(const float4*)&Kt[r * 64 + (c4 << 2)];
        }
        __syncthreads();

        // S = Q * K^T (each thread: 4x4 tile)
        float acc[4][4];
#pragma unroll
        for (int i = 0; i < 4; i++)
#pragma unroll
            for (int j = 0; j < 4; j++) acc[i][j] = 0.f;

#pragma unroll 8
        for (int d = 0; d < 64; d += 4) {
            float4 qv[4], kv[4];
#pragma unroll
            for (int i = 0; i < 4; i++)
                qv[i] = *(const float4*)&Qs[(str * 4 + i) * 64 + d];
#pragma unroll
            for (int j = 0; j < 4; j++)
                kv[j] = *(const float4*)&KVs[kvidx(stc * 4 + j, d >> 2)];
#pragma unroll
            for (int i = 0; i < 4; i++)
#pragma unroll
                for (int j = 0; j < 4; j++)
                    acc[i][j] += qv[i].x * kv[j].x + qv[i].y * kv[j].y +
                                 qv[i].z * kv[j].z + qv[i].w * kv[j].w;
        }
#pragma unroll
        for (int i = 0; i < 4; i++)
#pragma unroll
            for (int j = 0; j < 4; j++)
                Ss[(str * 4 + i) * 68 + stc * 4 + j] = acc[i][j] * 0.125f;
        __syncthreads();   // Ss ready; KVs free

        // Load V tile into KVs (overwrites K)
        const float* Vt = Vg + (size_t)kt * 64 * HD;
#pragma unroll
        for (int i = 0; i < 4; i++) {
            int id = t + i * 256;
            int r  = id >> 4;
            int c4 = id & 15;
            *(float4*)&KVs[kvidx(r, c4)] = *(const float4*)&Vt[r * 64 + (c4 << 2)];
        }

        // Online softmax on Ss (row = orow, cols og*16..og*16+15)
        float s[16];
#pragma unroll
        for (int i = 0; i < 16; i += 4)
            *(float4*)&s[i] = *(const float4*)&Ss[orow * 68 + og * 16 + i];
        float tm = s[0];
#pragma unroll
        for (int i = 1; i < 16; i++) tm = fmaxf(tm, s[i]);
        tm = fmaxf(tm, __shfl_xor_sync(0xffffffffu, tm, 1));
        tm = fmaxf(tm, __shfl_xor_sync(0xffffffffu, tm, 2));
        float mnew = fmaxf(m, tm);
        float corr = __expf(m - mnew);
        float ps = 0.f;
#pragma unroll
        for (int i = 0; i < 16; i++) { s[i] = __expf(s[i] - mnew); ps += s[i]; }
        ps += __shfl_xor_sync(0xffffffffu, ps, 1);
        ps += __shfl_xor_sync(0xffffffffu, ps, 2);
        l = l * corr + ps;
        m = mnew;
#pragma unroll
        for (int i = 0; i < 16; i++) o[i] *= corr;
#pragma unroll
        for (int i = 0; i < 16; i += 4)
            *(float4*)&Ss[orow * 68 + og * 16 + i] = *(const float4*)&s[i];
        __syncthreads();   // P and V ready

        // O += P * V
#pragma unroll 16
        for (int j = 0; j < 64; j++) {
            float p = Ss[orow * 68 + j];
#pragma unroll
            for (int i = 0; i < 16; i += 4) {
                float4 vv = *(const float4*)&KVs[kvidx(j, og * 4 + (i >> 2))];
                o[i]     += p * vv.x;
                o[i + 1] += p * vv.y;
                o[i + 2] += p * vv.z;
                o[i + 3] += p * vv.w;
            }
        }
    }

    float inv = 1.f / l;
    float* dst = g_att + (size_t)(qt * 64 + orow) * DIM + h * HD + og * 16;
#pragma unroll
    for (int i = 0; i < 16; i += 4) {
        float4 v;
        v.x = o[i] * inv; v.y = o[i + 1] * inv;
        v.z = o[i + 2] * inv; v.w = o[i + 3] * inv;
        *(float4*)&dst[i] = v;
    }
}

// ---------------------------------------------------------------------------
extern "C" void kernel_launch(void* const* d_in, const int* in_sizes, int n_in,
                              void* d_out, int out_size) {
    const float* x     = (const float*)d_in[0];
    const float* Wqkv  = (const float*)d_in[1];
    const float* bqkv  = (const float*)d_in[2];
    const float* Wproj = (const float*)d_in[3];
    const float* bproj = (const float*)d_in[4];
    float* out = (float*)d_out;

    // 1) QKV projection, scattered into [H, SEQ, HD] q/k/v buffers
    sgemm_k<3 * DIM, 0><<<dim3(24, 32), 256>>>(x, Wqkv, bqkv, nullptr);

    // 2) Flash attention
    const int shm = (4096 + 4096 + 64 * 68) * (int)sizeof(float);  // 50176 B
    cudaFuncSetAttribute(attn_kernel, cudaFuncAttributeMaxDynamicSharedMemorySize, shm);
    attn_kernel<<<dim3(SEQ / 64, NH), 256, shm>>>();

    // 3) Output projection
    sgemm_k<DIM, 1><<<dim3(8, 32), 256>>>(nullptr, Wproj, bproj, out);
}

// round 4
// speedup vs baseline: 4.5552x; 4.5552x over previous
#include <cuda_runtime.h>
#include <cstdint>

#define SEQ  4096
#define DIM  1024
#define NH   16
#define HD   64

// Scratch (allocation-free rule: __device__ globals)
__device__ float g_q[(size_t)NH * SEQ * HD];   // [H][SEQ][HD], tf32-rounded, pre-scaled 0.125
__device__ float g_k[(size_t)NH * SEQ * HD];   // [H][SEQ][HD], tf32-rounded
__device__ float g_v[(size_t)NH * SEQ * HD];   // [H][SEQ][HD], tf32-rounded
__device__ float g_att[(size_t)SEQ * DIM];

// ---------------------------------------------------------------------------
// Helpers (sm_100-base-target safe: no tcgen05, no mbarrier, no elect)
// ---------------------------------------------------------------------------
__device__ __forceinline__ uint32_t smem_u32(const void* p) {
    uint32_t a;
    asm("{ .reg .u64 t; cvta.to.shared.u64 t, %1; cvt.u32.u64 %0, t; }" : "=r"(a) : "l"(p));
    return a;
}
__device__ __forceinline__ float ex2f(float x) {
    float r; asm("ex2.approx.ftz.f32 %0, %1;" : "=f"(r) : "f"(x)); return r;
}
__device__ __forceinline__ float tf32_rna(float x) {
    uint32_t u; asm("cvt.rna.tf32.f32 %0, %1;" : "=r"(u) : "f"(x)); return __uint_as_float(u);
}
__device__ __forceinline__ void cp16(uint32_t dst, const void* src) {
    asm volatile("cp.async.cg.shared.global [%0], [%1], 16;" :: "r"(dst), "l"(src));
}
#define CP_COMMIT() asm volatile("cp.async.commit_group;" ::: "memory")
#define CP_WAIT1()  asm volatile("cp.async.wait_group 1;" ::: "memory")

// mma.sync m16n8k8 tf32 (sm_80+; legal under compute_100)
__device__ __forceinline__ void mma_tf32(float* d, const float* a, float b0, float b1) {
    asm volatile(
        "mma.sync.aligned.m16n8k8.row.col.f32.tf32.tf32.f32 "
        "{%0,%1,%2,%3}, {%4,%5,%6,%7}, {%8,%9}, {%0,%1,%2,%3};"
        : "+f"(d[0]), "+f"(d[1]), "+f"(d[2]), "+f"(d[3])
        : "r"(__float_as_uint(a[0])), "r"(__float_as_uint(a[1])),
          "r"(__float_as_uint(a[2])), "r"(__float_as_uint(a[3])),
          "r"(__float_as_uint(b0)), "r"(__float_as_uint(b1)));
}

#define LOG2E 1.44269504f

// ---------------------------------------------------------------------------
// SGEMM (SIMT fp32): C[M,N] = A[M,K]*B[K,N] + bias, K=1024.
// MODE 0: epilogue scatters tf32-rounded values into g_q/g_k/g_v.
// MODE 1: reads g_att, writes C.
// ---------------------------------------------------------------------------
template <int N_, int MODE>
__global__ __launch_bounds__(256) void sgemm_k(const float* __restrict__ A_in,
                                               const float* __restrict__ B,
                                               const float* __restrict__ bias,
                                               float* __restrict__ C) {
    const int K = DIM;
    const float* A = (MODE == 1) ? g_att : A_in;

    __shared__ float As[16][128];
    __shared__ float Bs[16][128];

    const int t  = threadIdx.x;
    const int tx = t & 15;
    const int ty = t >> 4;
    const int rowBase = blockIdx.y * 128;
    const int colBase = blockIdx.x * 128;

    float acc[8][8];
#pragma unroll
    for (int i = 0; i < 8; i++)
#pragma unroll
        for (int j = 0; j < 8; j++) acc[i][j] = 0.f;

    for (int k0 = 0; k0 < K; k0 += 16) {
#pragma unroll
        for (int i = 0; i < 2; i++) {
            int id = t + i * 256;
            int r  = id >> 2;
            int kk = (id & 3) << 2;
            float4 v = *(const float4*)&A[(size_t)(rowBase + r) * K + k0 + kk];
            As[kk + 0][r] = v.x; As[kk + 1][r] = v.y;
            As[kk + 2][r] = v.z; As[kk + 3][r] = v.w;
        }
#pragma unroll
        for (int i = 0; i < 2; i++) {
            int id = t + i * 256;
            int r  = id >> 5;
            int c  = (id & 31) << 2;
            *(float4*)&Bs[r][c] = *(const float4*)&B[(size_t)(k0 + r) * N_ + colBase + c];
        }
        __syncthreads();

#pragma unroll
        for (int kk = 0; kk < 16; kk++) {
            float a[8], b[8];
            *(float4*)&a[0] = *(const float4*)&As[kk][ty * 8];
            *(float4*)&a[4] = *(const float4*)&As[kk][ty * 8 + 4];
            *(float4*)&b[0] = *(const float4*)&Bs[kk][tx * 8];
            *(float4*)&b[4] = *(const float4*)&Bs[kk][tx * 8 + 4];
#pragma unroll
            for (int i = 0; i < 8; i++)
#pragma unroll
                for (int j = 0; j < 8; j++) acc[i][j] += a[i] * b[j];
        }
        __syncthreads();
    }

#pragma unroll
    for (int i = 0; i < 8; i++) {
        int r = rowBase + ty * 8 + i;
#pragma unroll
        for (int j = 0; j < 8; j++) {
            int cg = colBase + tx * 8 + j;
            float v = acc[i][j] + bias[cg];
            if (MODE == 0) {
                int which = cg >> 10;
                int c2    = cg & 1023;
                int head  = c2 >> 6;
                int d     = c2 & 63;
                if (which == 0)
                    g_q[((size_t)head * SEQ + r) * HD + d] = tf32_rna(v * 0.125f);
                else if (which == 1)
                    g_k[((size_t)head * SEQ + r) * HD + d] = tf32_rna(v);
                else
                    g_v[((size_t)head * SEQ + r) * HD + d] = tf32_rna(v);
            } else {
                C[(size_t)r * N_ + cg] = v;
            }
        }
    }
}

// ---------------------------------------------------------------------------
// Warp-MMA tf32 flash attention.
// Block = 64 q-rows x 1 head, 128 threads (4 warps, 16 rows each).
// Key tiles of 64, double-buffered cp.async.
// SMEM (floats, stride 68 rows for conflict-free fragment reads):
//   stage s: K at s*8704, V at s*8704+4352 ; Ps (P tile / Q staging) at 17408.
// Total 21760 floats = 87040 B -> 2 blocks/SM.
// ---------------------------------------------------------------------------
#define PSTR 68
#define KV_STAGE_F 8704          // floats per (K,V) stage
#define PS_OFF_F   17408         // Ps offset in floats

__global__ __launch_bounds__(128, 2) void attn_mma() {
    extern __shared__ float sm[];
    const uint32_t sb = smem_u32(sm);
    float* Ps = sm + PS_OFF_F;

    const int t    = threadIdx.x;
    const int w    = t >> 5;
    const int lane = t & 31;
    const int lr   = lane >> 2;      // fragment group id (row within 8)
    const int lc   = lane & 3;       // thread id in group
    const int w16  = w * 16;
    const int h  = blockIdx.y;
    const int qt = blockIdx.x;

    const float* Kh = g_k + (size_t)h * SEQ * HD;
    const float* Vh = g_v + (size_t)h * SEQ * HD;

    // prefetch one (K,V) pair for tile kt2 into stage s
    auto load_stage = [&](int kt2, int s) {
#pragma unroll
        for (int i = 0; i < 16; i++) {
            int id   = t + i * 128;            // 0..2047
            int tile = id >> 10;               // 0=K 1=V
            int r    = (id >> 4) & 63;
            int c4   = id & 15;
            uint32_t dst = sb + (uint32_t)s * (KV_STAGE_F * 4)
                              + (uint32_t)tile * (64 * PSTR * 4)
                              + (uint32_t)r * (PSTR * 4) + (uint32_t)c4 * 16;
            const float* src = (tile ? Vh : Kh) + ((size_t)kt2 * 64 + r) * HD + c4 * 4;
            cp16(dst, src);
        }
        CP_COMMIT();
    };

    load_stage(0, 0);
    load_stage(1, 1);

    // Stage Q tile through Ps, then load A-fragments to registers
    {
        const float* Qg = g_q + ((size_t)h * SEQ + (size_t)qt * 64) * HD;
#pragma unroll
        for (int i = 0; i < 8; i++) {
            int id = t + i * 128;              // float4 units, 0..1023
            int r  = id >> 4;
            int c  = (id & 15) * 4;
            *(float4*)&Ps[r * PSTR + c] = *(const float4*)&Qg[r * HD + c];
        }
    }
    __syncthreads();
    float qf[8][4];
#pragma unroll
    for (int k = 0; k < 8; k++) {
        qf[k][0] = Ps[(w16 + lr) * PSTR + k * 8 + lc];
        qf[k][1] = Ps[(w16 + lr + 8) * PSTR + k * 8 + lc];
        qf[k][2] = Ps[(w16 + lr) * PSTR + k * 8 + lc + 4];
        qf[k][3] = Ps[(w16 + lr + 8) * PSTR + k * 8 + lc + 4];
    }
    __syncthreads();

    float ob[8][4];
#pragma unroll
    for (int j = 0; j < 8; j++)
#pragma unroll
        for (int i = 0; i < 4; i++) ob[j][i] = 0.f;
    float m0 = -1e30f, m1 = -1e30f, l0 = 0.f, l1 = 0.f;

    for (int kt = 0; kt < SEQ / 64; kt++) {
        const int s = kt & 1;
        const float* Ks = sm + s * KV_STAGE_F;
        const float* Vs = Ks + 64 * PSTR;

        CP_WAIT1();
        __syncthreads();   // stage ready; also: all warps past prev PV (Ps reusable)

        // ---- S = Q * K^T  (per warp: 16x64) ----
        float sc[8][4];
#pragma unroll
        for (int j = 0; j < 8; j++)
#pragma unroll
            for (int i = 0; i < 4; i++) sc[j][i] = 0.f;
#pragma unroll
        for (int k = 0; k < 8; k++) {
#pragma unroll
            for (int j = 0; j < 8; j++) {
                float b0 = Ks[(j * 8 + lr) * PSTR + k * 8 + lc];
                float b1 = Ks[(j * 8 + lr) * PSTR + k * 8 + lc + 4];
                mma_tf32(sc[j], qf[k], b0, b1);
            }
        }

        // ---- online softmax (thread rows: w16+lr and w16+lr+8) ----
        float mx0 = sc[0][0], mx1 = sc[0][2];
#pragma unroll
        for (int j = 0; j < 8; j++) {
            mx0 = fmaxf(mx0, fmaxf(sc[j][0], sc[j][1]));
            mx1 = fmaxf(mx1, fmaxf(sc[j][2], sc[j][3]));
        }
        mx0 = fmaxf(mx0, __shfl_xor_sync(0xffffffffu, mx0, 1));
        mx0 = fmaxf(mx0, __shfl_xor_sync(0xffffffffu, mx0, 2));
        mx1 = fmaxf(mx1, __shfl_xor_sync(0xffffffffu, mx1, 1));
        mx1 = fmaxf(mx1, __shfl_xor_sync(0xffffffffu, mx1, 2));
        float nm0 = fmaxf(m0, mx0), nm1 = fmaxf(m1, mx1);
        float corr0 = ex2f((m0 - nm0) * LOG2E);
        float corr1 = ex2f((m1 - nm1) * LOG2E);
        float s0 = 0.f, s1 = 0.f;
#pragma unroll
        for (int j = 0; j < 8; j++) {
            float p00 = ex2f((sc[j][0] - nm0) * LOG2E);
            float p01 = ex2f((sc[j][1] - nm0) * LOG2E);
            float p10 = ex2f((sc[j][2] - nm1) * LOG2E);
            float p11 = ex2f((sc[j][3] - nm1) * LOG2E);
            s0 += p00 + p01;
            s1 += p10 + p11;
            float2 v0 = make_float2(tf32_rna(p00), tf32_rna(p01));
            float2 v1 = make_float2(tf32_rna(p10), tf32_rna(p11));
            *(float2*)&Ps[(w16 + lr) * PSTR + j * 8 + lc * 2]     = v0;
            *(float2*)&Ps[(w16 + lr + 8) * PSTR + j * 8 + lc * 2] = v1;
        }
        s0 += __shfl_xor_sync(0xffffffffu, s0, 1);
        s0 += __shfl_xor_sync(0xffffffffu, s0, 2);
        s1 += __shfl_xor_sync(0xffffffffu, s1, 1);
        s1 += __shfl_xor_sync(0xffffffffu, s1, 2);
        l0 = l0 * corr0 + s0;  m0 = nm0;
        l1 = l1 * corr1 + s1;  m1 = nm1;
#pragma unroll
        for (int j = 0; j < 8; j++) {
            ob[j][0] *= corr0; ob[j][1] *= corr0;
            ob[j][2] *= corr1; ob[j][3] *= corr1;
        }
        __syncthreads();   // Ps written by all warps

        // ---- O += P * V  (A = P rows from Ps, B = V k-major over keys) ----
#pragma unroll
        for (int k = 0; k < 8; k++) {
            float pf[4];
            pf[0] = Ps[(w16 + lr) * PSTR + k * 8 + lc];
            pf[1] = Ps[(w16 + lr + 8) * PSTR + k * 8 + lc];
            pf[2] = Ps[(w16 + lr) * PSTR + k * 8 + lc + 4];
            pf[3] = Ps[(w16 + lr + 8) * PSTR + k * 8 + lc + 4];
#pragma unroll
            for (int j = 0; j < 8; j++) {
                float b0 = Vs[(k * 8 + lc) * PSTR + j * 8 + lr];
                float b1 = Vs[(k * 8 + lc + 4) * PSTR + j * 8 + lr];
                mma_tf32(ob[j], pf, b0, b1);
            }
        }
        __syncthreads();   // stage s fully consumed

        if (kt + 2 < SEQ / 64) load_stage(kt + 2, s);
        else CP_COMMIT();  // keep group accounting uniform
    }

    // ---- write output rows ----
    float inv0 = 1.f / l0, inv1 = 1.f / l1;
    float* d0 = g_att + ((size_t)qt * 64 + w16 + lr) * DIM + h * HD;
    float* d1 = d0 + 8 * DIM;
#pragma unroll
    for (int j = 0; j < 8; j++) {
        *(float2*)&d0[j * 8 + lc * 2] = make_float2(ob[j][0] * inv0, ob[j][1] * inv0);
        *(float2*)&d1[j * 8 + lc * 2] = make_float2(ob[j][2] * inv1, ob[j][3] * inv1);
    }
}

// ---------------------------------------------------------------------------
extern "C" void kernel_launch(void* const* d_in, const int* in_sizes, int n_in,
                              void* d_out, int out_size) {
    const float* x     = (const float*)d_in[0];
    const float* Wqkv  = (const float*)d_in[1];
    const float* bqkv  = (const float*)d_in[2];
    const float* Wproj = (const float*)d_in[3];
    const float* bproj = (const float*)d_in[4];
    float* out = (float*)d_out;

    // 1) QKV projection -> tf32-rounded q (scaled), k, v in [H,SEQ,HD]
    sgemm_k<3 * DIM, 0><<<dim3(24, 32), 256>>>(x, Wqkv, bqkv, nullptr);

    // 2) warp-MMA tf32 flash attention
    const int shm = (2 * KV_STAGE_F + 64 * PSTR) * (int)sizeof(float);  // 87040 B
    cudaFuncSetAttribute(attn_mma, cudaFuncAttributeMaxDynamicSharedMemorySize, shm);
    attn_mma<<<dim3(SEQ / 64, NH), 128, shm>>>();

    // 3) Output projection (fp32 SIMT)
    sgemm_k<DIM, 1><<<dim3(8, 32), 256>>>(nullptr, Wproj, bproj, out);
}

// round 5
// speedup vs baseline: 7.2386x; 1.5891x over previous
#include <cuda_runtime.h>
#include <cstdint>

#define SEQ  4096
#define DIM  1024
#define NH   16
#define HD   64

// Scratch (allocation-free rule: __device__ globals)
__device__ float g_q[(size_t)NH * SEQ * HD];   // [H][SEQ][HD], tf32-rounded, pre-scaled 0.125
__device__ float g_k[(size_t)NH * SEQ * HD];   // [H][SEQ][HD], tf32-rounded
__device__ float g_v[(size_t)NH * SEQ * HD];   // [H][SEQ][HD], tf32-rounded
__device__ float g_att[(size_t)SEQ * DIM];

// ---------------------------------------------------------------------------
// Helpers (sm_100-base-target safe)
// ---------------------------------------------------------------------------
__device__ __forceinline__ uint32_t smem_u32(const void* p) {
    uint32_t a;
    asm("{ .reg .u64 t; cvta.to.shared.u64 t, %1; cvt.u32.u64 %0, t; }" : "=r"(a) : "l"(p));
    return a;
}
__device__ __forceinline__ float ex2f(float x) {
    float r; asm("ex2.approx.ftz.f32 %0, %1;" : "=f"(r) : "f"(x)); return r;
}
__device__ __forceinline__ float tf32_rna(float x) {
    uint32_t u; asm("cvt.rna.tf32.f32 %0, %1;" : "=r"(u) : "f"(x)); return __uint_as_float(u);
}
__device__ __forceinline__ void cp16(uint32_t dst, const void* src) {
    asm volatile("cp.async.cg.shared.global [%0], [%1], 16;" :: "r"(dst), "l"(src));
}
#define CP_COMMIT() asm volatile("cp.async.commit_group;" ::: "memory")
#define CP_WAIT1()  asm volatile("cp.async.wait_group 1;" ::: "memory")

// mma.sync m16n8k8 tf32 (sm_80+; legal under compute_100)
__device__ __forceinline__ void mma_tf32(float* d, const float* a, float b0, float b1) {
    asm volatile(
        "mma.sync.aligned.m16n8k8.row.col.f32.tf32.tf32.f32 "
        "{%0,%1,%2,%3}, {%4,%5,%6,%7}, {%8,%9}, {%0,%1,%2,%3};"
        : "+f"(d[0]), "+f"(d[1]), "+f"(d[2]), "+f"(d[3])
        : "r"(__float_as_uint(a[0])), "r"(__float_as_uint(a[1])),
          "r"(__float_as_uint(a[2])), "r"(__float_as_uint(a[3])),
          "r"(__float_as_uint(b0)), "r"(__float_as_uint(b1)));
}

#define LOG2E 1.44269504f

// ---------------------------------------------------------------------------
// tf32 warp-MMA GEMM: C[M,N_] = A[M,1024]*B[1024,N_] + bias.
// Block 128x128, 8 warps (2x4), warp tile 64x32, k-chunk 16, double-buffered.
// SMEM: A [128][20] floats, B [16][136] floats per stage (conflict-free frags).
// MODE 0: scatter tf32-rounded into g_q (x0.125) / g_k / g_v.  MODE 1: plain C.
// ---------------------------------------------------------------------------
#define ASTR 20
#define BSTR 136
#define A_ST_F (128 * ASTR)            // 2560 floats
#define B_ST_F (16 * BSTR)             // 2176 floats
#define STG_F  (A_ST_F + B_ST_F)       // 4736 floats / stage

template <int N_, int MODE>
__global__ __launch_bounds__(256) void gemm_tc(const float* __restrict__ A_in,
                                               const float* __restrict__ B,
                                               const float* __restrict__ bias,
                                               float* __restrict__ C) {
    extern __shared__ float sm[];
    const uint32_t sb = smem_u32(sm);
    const int K = DIM;
    const float* A = (MODE == 1) ? g_att : A_in;

    const int t    = threadIdx.x;
    const int w    = t >> 5;
    const int lane = t & 31;
    const int lr   = lane >> 2;
    const int lc   = lane & 3;
    const int wm   = (w >> 2) * 64;    // warp m offset (0 or 64)
    const int wn   = (w & 3) * 32;     // warp n offset
    const int rowBase = blockIdx.y * 128;
    const int colBase = blockIdx.x * 128;

    auto load_chunk = [&](int k0, int s) {
        uint32_t base = sb + (uint32_t)s * (STG_F * 4);
#pragma unroll
        for (int i = 0; i < 2; i++) {           // A: 128 rows x 4 float4
            int id = t + i * 256;
            int r  = id >> 2;
            int c4 = id & 3;
            cp16(base + (uint32_t)r * (ASTR * 4) + (uint32_t)c4 * 16,
                 A + (size_t)(rowBase + r) * K + k0 + c4 * 4);
        }
#pragma unroll
        for (int i = 0; i < 2; i++) {           // B: 16 rows x 32 float4
            int id = t + i * 256;
            int r  = id >> 5;
            int c4 = id & 31;
            cp16(base + (uint32_t)(A_ST_F * 4) + (uint32_t)r * (BSTR * 4) + (uint32_t)c4 * 16,
                 B + (size_t)(k0 + r) * N_ + colBase + c4 * 4);
        }
        CP_COMMIT();
    };

    load_chunk(0, 0);
    load_chunk(16, 1);

    float acc[4][4][4];
#pragma unroll
    for (int mt = 0; mt < 4; mt++)
#pragma unroll
        for (int nt = 0; nt < 4; nt++)
#pragma unroll
            for (int i = 0; i < 4; i++) acc[mt][nt][i] = 0.f;

    for (int kc = 0; kc < K / 16; kc++) {
        const int s = kc & 1;
        const float* As = sm + s * STG_F;
        const float* Bs = As + A_ST_F;

        CP_WAIT1();
        __syncthreads();

#pragma unroll
        for (int kk = 0; kk < 2; kk++) {
            const int k = kk * 8;
            float af[4][4];
#pragma unroll
            for (int mt = 0; mt < 4; mt++) {
                int mb = wm + mt * 16;
                af[mt][0] = tf32_rna(As[(mb + lr) * ASTR + k + lc]);
                af[mt][1] = tf32_rna(As[(mb + lr + 8) * ASTR + k + lc]);
                af[mt][2] = tf32_rna(As[(mb + lr) * ASTR + k + lc + 4]);
                af[mt][3] = tf32_rna(As[(mb + lr + 8) * ASTR + k + lc + 4]);
            }
            float bf[4][2];
#pragma unroll
            for (int nt = 0; nt < 4; nt++) {
                int n = wn + nt * 8 + lr;
                bf[nt][0] = tf32_rna(Bs[(k + lc) * BSTR + n]);
                bf[nt][1] = tf32_rna(Bs[(k + lc + 4) * BSTR + n]);
            }
#pragma unroll
            for (int mt = 0; mt < 4; mt++)
#pragma unroll
                for (int nt = 0; nt < 4; nt++)
                    mma_tf32(acc[mt][nt], af[mt], bf[nt][0], bf[nt][1]);
        }
        __syncthreads();

        if (kc + 2 < K / 16) load_chunk((kc + 2) * 16, s);
        else CP_COMMIT();
    }

    // Epilogue
#pragma unroll
    for (int nt = 0; nt < 4; nt++) {
        int c = colBase + wn + nt * 8 + 2 * lc;
        float2 bv = *(const float2*)&bias[c];
#pragma unroll
        for (int mt = 0; mt < 4; mt++) {
            int r0 = rowBase + wm + mt * 16 + lr;
            int r1 = r0 + 8;
            float v00 = acc[mt][nt][0] + bv.x, v01 = acc[mt][nt][1] + bv.y;
            float v10 = acc[mt][nt][2] + bv.x, v11 = acc[mt][nt][3] + bv.y;
            if (MODE == 0) {
                int which = c >> 10;
                int c2    = c & 1023;
                int head  = c2 >> 6;
                int d     = c2 & 63;
                if (which == 0) {
                    float* dq = g_q + ((size_t)head * SEQ) * HD + d;
                    *(float2*)&dq[(size_t)r0 * HD] =
                        make_float2(tf32_rna(v00 * 0.125f), tf32_rna(v01 * 0.125f));
                    *(float2*)&dq[(size_t)r1 * HD] =
                        make_float2(tf32_rna(v10 * 0.125f), tf32_rna(v11 * 0.125f));
                } else {
                    float* dst = ((which == 1) ? g_k : g_v) + ((size_t)head * SEQ) * HD + d;
                    *(float2*)&dst[(size_t)r0 * HD] =
                        make_float2(tf32_rna(v00), tf32_rna(v01));
                    *(float2*)&dst[(size_t)r1 * HD] =
                        make_float2(tf32_rna(v10), tf32_rna(v11));
                }
            } else {
                *(float2*)&C[(size_t)r0 * N_ + c] = make_float2(v00, v01);
                *(float2*)&C[(size_t)r1 * N_ + c] = make_float2(v10, v11);
            }
        }
    }
}

// ---------------------------------------------------------------------------
// Warp-MMA tf32 flash attention (unchanged from round 4: measured 3.17e-4).
// Block = 64 q-rows x 1 head, 128 threads (4 warps, 16 rows each).
// ---------------------------------------------------------------------------
#define PSTR 68
#define KV_STAGE_F 8704
#define PS_OFF_F   17408

__global__ __launch_bounds__(128, 2) void attn_mma() {
    extern __shared__ float sm[];
    const uint32_t sb = smem_u32(sm);
    float* Ps = sm + PS_OFF_F;

    const int t    = threadIdx.x;
    const int w    = t >> 5;
    const int lane = t & 31;
    const int lr   = lane >> 2;
    const int lc   = lane & 3;
    const int w16  = w * 16;
    const int h  = blockIdx.y;
    const int qt = blockIdx.x;

    const float* Kh = g_k + (size_t)h * SEQ * HD;
    const float* Vh = g_v + (size_t)h * SEQ * HD;

    auto load_stage = [&](int kt2, int s) {
#pragma unroll
        for (int i = 0; i < 16; i++) {
            int id   = t + i * 128;
            int tile = id >> 10;
            int r    = (id >> 4) & 63;
            int c4   = id & 15;
            uint32_t dst = sb + (uint32_t)s * (KV_STAGE_F * 4)
                              + (uint32_t)tile * (64 * PSTR * 4)
                              + (uint32_t)r * (PSTR * 4) + (uint32_t)c4 * 16;
            const float* src = (tile ? Vh : Kh) + ((size_t)kt2 * 64 + r) * HD + c4 * 4;
            cp16(dst, src);
        }
        CP_COMMIT();
    };

    load_stage(0, 0);
    load_stage(1, 1);

    {
        const float* Qg = g_q + ((size_t)h * SEQ + (size_t)qt * 64) * HD;
#pragma unroll
        for (int i = 0; i < 8; i++) {
            int id = t + i * 128;
            int r  = id >> 4;
            int c  = (id & 15) * 4;
            *(float4*)&Ps[r * PSTR + c] = *(const float4*)&Qg[r * HD + c];
        }
    }
    __syncthreads();
    float qf[8][4];
#pragma unroll
    for (int k = 0; k < 8; k++) {
        qf[k][0] = Ps[(w16 + lr) * PSTR + k * 8 + lc];
        qf[k][1] = Ps[(w16 + lr + 8) * PSTR + k * 8 + lc];
        qf[k][2] = Ps[(w16 + lr) * PSTR + k * 8 + lc + 4];
        qf[k][3] = Ps[(w16 + lr + 8) * PSTR + k * 8 + lc + 4];
    }
    __syncthreads();

    float ob[8][4];
#pragma unroll
    for (int j = 0; j < 8; j++)
#pragma unroll
        for (int i = 0; i < 4; i++) ob[j][i] = 0.f;
    float m0 = -1e30f, m1 = -1e30f, l0 = 0.f, l1 = 0.f;

    for (int kt = 0; kt < SEQ / 64; kt++) {
        const int s = kt & 1;
        const float* Ks = sm + s * KV_STAGE_F;
        const float* Vs = Ks + 64 * PSTR;

        CP_WAIT1();
        __syncthreads();

        float sc[8][4];
#pragma unroll
        for (int j = 0; j < 8; j++)
#pragma unroll
            for (int i = 0; i < 4; i++) sc[j][i] = 0.f;
#pragma unroll
        for (int k = 0; k < 8; k++) {
#pragma unroll
            for (int j = 0; j < 8; j++) {
                float b0 = Ks[(j * 8 + lr) * PSTR + k * 8 + lc];
                float b1 = Ks[(j * 8 + lr) * PSTR + k * 8 + lc + 4];
                mma_tf32(sc[j], qf[k], b0, b1);
            }
        }

        float mx0 = sc[0][0], mx1 = sc[0][2];
#pragma unroll
        for (int j = 0; j < 8; j++) {
            mx0 = fmaxf(mx0, fmaxf(sc[j][0], sc[j][1]));
            mx1 = fmaxf(mx1, fmaxf(sc[j][2], sc[j][3]));
        }
        mx0 = fmaxf(mx0, __shfl_xor_sync(0xffffffffu, mx0, 1));
        mx0 = fmaxf(mx0, __shfl_xor_sync(0xffffffffu, mx0, 2));
        mx1 = fmaxf(mx1, __shfl_xor_sync(0xffffffffu, mx1, 1));
        mx1 = fmaxf(mx1, __shfl_xor_sync(0xffffffffu, mx1, 2));
        float nm0 = fmaxf(m0, mx0), nm1 = fmaxf(m1, mx1);
        float corr0 = ex2f((m0 - nm0) * LOG2E);
        float corr1 = ex2f((m1 - nm1) * LOG2E);
        float s0 = 0.f, s1 = 0.f;
#pragma unroll
        for (int j = 0; j < 8; j++) {
            float p00 = ex2f((sc[j][0] - nm0) * LOG2E);
            float p01 = ex2f((sc[j][1] - nm0) * LOG2E);
            float p10 = ex2f((sc[j][2] - nm1) * LOG2E);
            float p11 = ex2f((sc[j][3] - nm1) * LOG2E);
            s0 += p00 + p01;
            s1 += p10 + p11;
            float2 v0 = make_float2(tf32_rna(p00), tf32_rna(p01));
            float2 v1 = make_float2(tf32_rna(p10), tf32_rna(p11));
            *(float2*)&Ps[(w16 + lr) * PSTR + j * 8 + lc * 2]     = v0;
            *(float2*)&Ps[(w16 + lr + 8) * PSTR + j * 8 + lc * 2] = v1;
        }
        s0 += __shfl_xor_sync(0xffffffffu, s0, 1);
        s0 += __shfl_xor_sync(0xffffffffu, s0, 2);
        s1 += __shfl_xor_sync(0xffffffffu, s1, 1);
        s1 += __shfl_xor_sync(0xffffffffu, s1, 2);
        l0 = l0 * corr0 + s0;  m0 = nm0;
        l1 = l1 * corr1 + s1;  m1 = nm1;
#pragma unroll
        for (int j = 0; j < 8; j++) {
            ob[j][0] *= corr0; ob[j][1] *= corr0;
            ob[j][2] *= corr1; ob[j][3] *= corr1;
        }
        __syncthreads();

#pragma unroll
        for (int k = 0; k < 8; k++) {
            float pf[4];
            pf[0] = Ps[(w16 + lr) * PSTR + k * 8 + lc];
            pf[1] = Ps[(w16 + lr + 8) * PSTR + k * 8 + lc];
            pf[2] = Ps[(w16 + lr) * PSTR + k * 8 + lc + 4];
            pf[3] = Ps[(w16 + lr + 8) * PSTR + k * 8 + lc + 4];
#pragma unroll
            for (int j = 0; j < 8; j++) {
                float b0 = Vs[(k * 8 + lc) * PSTR + j * 8 + lr];
                float b1 = Vs[(k * 8 + lc + 4) * PSTR + j * 8 + lr];
                mma_tf32(ob[j], pf, b0, b1);
            }
        }
        __syncthreads();

        if (kt + 2 < SEQ / 64) load_stage(kt + 2, s);
        else CP_COMMIT();
    }

    float inv0 = 1.f / l0, inv1 = 1.f / l1;
    float* d0 = g_att + ((size_t)qt * 64 + w16 + lr) * DIM + h * HD;
    float* d1 = d0 + 8 * DIM;
#pragma unroll
    for (int j = 0; j < 8; j++) {
        *(float2*)&d0[j * 8 + lc * 2] = make_float2(ob[j][0] * inv0, ob[j][1] * inv0);
        *(float2*)&d1[j * 8 + lc * 2] = make_float2(ob[j][2] * inv1, ob[j][3] * inv1);
    }
}

// ---------------------------------------------------------------------------
extern "C" void kernel_launch(void* const* d_in, const int* in_sizes, int n_in,
                              void* d_out, int out_size) {
    const float* x     = (const float*)d_in[0];
    const float* Wqkv  = (const float*)d_in[1];
    const float* bqkv  = (const float*)d_in[2];
    const float* Wproj = (const float*)d_in[3];
    const float* bproj = (const float*)d_in[4];
    float* out = (float*)d_out;

    const int gemm_shm = 2 * STG_F * (int)sizeof(float);   // 37888 B
    const int attn_shm = (2 * KV_STAGE_F + 64 * PSTR) * (int)sizeof(float);  // 87040 B

    // 1) QKV projection (tf32 MMA) -> q (scaled), k, v in [H,SEQ,HD]
    cudaFuncSetAttribute(gemm_tc<3 * DIM, 0>, cudaFuncAttributeMaxDynamicSharedMemorySize, gemm_shm);
    gemm_tc<3 * DIM, 0><<<dim3(24, 32), 256, gemm_shm>>>(x, Wqkv, bqkv, nullptr);

    // 2) warp-MMA tf32 flash attention
    cudaFuncSetAttribute(attn_mma, cudaFuncAttributeMaxDynamicSharedMemorySize, attn_shm);
    attn_mma<<<dim3(SEQ / 64, NH), 128, attn_shm>>>();

    // 3) Output projection (tf32 MMA)
    cudaFuncSetAttribute(gemm_tc<DIM, 1>, cudaFuncAttributeMaxDynamicSharedMemorySize, gemm_shm);
    gemm_tc<DIM, 1><<<dim3(8, 32), 256, gemm_shm>>>(nullptr, Wproj, bproj, out);
}

// round 6
// speedup vs baseline: 7.3595x; 1.0167x over previous
#include <cuda_runtime.h>
#include <cstdint>

#define SEQ  4096
#define DIM  1024
#define NH   16
#define HD   64

// Scratch (allocation-free rule: __device__ globals)
__device__ float g_q[(size_t)NH * SEQ * HD];   // tf32-rounded, pre-scaled 0.125
__device__ float g_k[(size_t)NH * SEQ * HD];
__device__ float g_v[(size_t)NH * SEQ * HD];
__device__ float g_att[(size_t)SEQ * DIM];     // tf32-rounded (attn epilogue)
__device__ float g_x [(size_t)SEQ * DIM];      // tf32-rounded x
__device__ float g_wq[(size_t)DIM * 3 * DIM];  // tf32-rounded W_qkv
__device__ float g_wp[(size_t)DIM * DIM];      // tf32-rounded W_proj

// ---------------------------------------------------------------------------
__device__ __forceinline__ uint32_t smem_u32(const void* p) {
    uint32_t a;
    asm("{ .reg .u64 t; cvta.to.shared.u64 t, %1; cvt.u32.u64 %0, t; }" : "=r"(a) : "l"(p));
    return a;
}
__device__ __forceinline__ float ex2f(float x) {
    float r; asm("ex2.approx.ftz.f32 %0, %1;" : "=f"(r) : "f"(x)); return r;
}
__device__ __forceinline__ float tf32_rna(float x) {
    uint32_t u; asm("cvt.rna.tf32.f32 %0, %1;" : "=r"(u) : "f"(x)); return __uint_as_float(u);
}
__device__ __forceinline__ void cp16(uint32_t dst, const void* src) {
    asm volatile("cp.async.cg.shared.global [%0], [%1], 16;" :: "r"(dst), "l"(src));
}
#define CP_COMMIT() asm volatile("cp.async.commit_group;" ::: "memory")
#define CP_WAIT1()  asm volatile("cp.async.wait_group 1;" ::: "memory")

// mma.sync m16n8k8 tf32 (sm_80+; legal under compute_100)
__device__ __forceinline__ void mma_tf32(float* d, const float* a, float b0, float b1) {
    asm volatile(
        "mma.sync.aligned.m16n8k8.row.col.f32.tf32.tf32.f32 "
        "{%0,%1,%2,%3}, {%4,%5,%6,%7}, {%8,%9}, {%0,%1,%2,%3};"
        : "+f"(d[0]), "+f"(d[1]), "+f"(d[2]), "+f"(d[3])
        : "r"(__float_as_uint(a[0])), "r"(__float_as_uint(a[1])),
          "r"(__float_as_uint(a[2])), "r"(__float_as_uint(a[3])),
          "r"(__float_as_uint(b0)), "r"(__float_as_uint(b1)));
}

#define LOG2E 1.44269504f

// ---------------------------------------------------------------------------
// Pre-round x / W_qkv / W_proj to tf32 (RNA) once per launch.
// ---------------------------------------------------------------------------
#define XN   ((size_t)SEQ * DIM)                 // 4194304
#define WQN  ((size_t)DIM * 3 * DIM)             // 3145728
#define WPN  ((size_t)DIM * DIM)                 // 1048576
#define TOT4 ((XN + WQN + WPN) / 4)              // 2097152 float4s

__global__ __launch_bounds__(256) void pre_round(const float* __restrict__ x,
                                                 const float* __restrict__ wq,
                                                 const float* __restrict__ wp) {
    size_t i = (size_t)blockIdx.x * blockDim.x + threadIdx.x;
    if (i >= TOT4) return;
    const float* src;
    float* dst;
    size_t off;
    if (i < XN / 4)                { src = x;  dst = g_x;  off = i; }
    else if (i < (XN + WQN) / 4)   { src = wq; dst = g_wq; off = i - XN / 4; }
    else                           { src = wp; dst = g_wp; off = i - (XN + WQN) / 4; }
    float4 v = ((const float4*)src)[off];
    v.x = tf32_rna(v.x); v.y = tf32_rna(v.y);
    v.z = tf32_rna(v.z); v.w = tf32_rna(v.w);
    ((float4*)dst)[off] = v;
}

// ---------------------------------------------------------------------------
// tf32 warp-MMA GEMM (inputs pre-rounded: raw fragment loads, no CVT).
// Block 128x128, 8 warps (2x4), warp tile 64x32, k-chunk 16, double-buffered.
// MODE 0: A=g_x, B=g_wq, scatter into g_q(x0.125)/g_k/g_v.  MODE 1: A=g_att,
// B=g_wp, write C.
// ---------------------------------------------------------------------------
#define ASTR 20
#define BSTR 136
#define A_ST_F (128 * ASTR)
#define B_ST_F (16 * BSTR)
#define STG_F  (A_ST_F + B_ST_F)

template <int N_, int MODE>
__global__ __launch_bounds__(256) void gemm_tc(const float* __restrict__ bias,
                                               float* __restrict__ C) {
    extern __shared__ float sm[];
    const uint32_t sb = smem_u32(sm);
    const int K = DIM;
    const float* A = (MODE == 1) ? g_att : g_x;
    const float* B = (MODE == 1) ? g_wp : g_wq;

    const int t    = threadIdx.x;
    const int w    = t >> 5;
    const int lane = t & 31;
    const int lr   = lane >> 2;
    const int lc   = lane & 3;
    const int wm   = (w >> 2) * 64;
    const int wn   = (w & 3) * 32;
    const int rowBase = blockIdx.y * 128;
    const int colBase = blockIdx.x * 128;

    auto load_chunk = [&](int k0, int s) {
        uint32_t base = sb + (uint32_t)s * (STG_F * 4);
#pragma unroll
        for (int i = 0; i < 2; i++) {
            int id = t + i * 256;
            int r  = id >> 2;
            int c4 = id & 3;
            cp16(base + (uint32_t)r * (ASTR * 4) + (uint32_t)c4 * 16,
                 A + (size_t)(rowBase + r) * K + k0 + c4 * 4);
        }
#pragma unroll
        for (int i = 0; i < 2; i++) {
            int id = t + i * 256;
            int r  = id >> 5;
            int c4 = id & 31;
            cp16(base + (uint32_t)(A_ST_F * 4) + (uint32_t)r * (BSTR * 4) + (uint32_t)c4 * 16,
                 B + (size_t)(k0 + r) * N_ + colBase + c4 * 4);
        }
        CP_COMMIT();
    };

    load_chunk(0, 0);
    load_chunk(16, 1);

    float acc[4][4][4];
#pragma unroll
    for (int mt = 0; mt < 4; mt++)
#pragma unroll
        for (int nt = 0; nt < 4; nt++)
#pragma unroll
            for (int i = 0; i < 4; i++) acc[mt][nt][i] = 0.f;

    for (int kc = 0; kc < K / 16; kc++) {
        const int s = kc & 1;
        const float* As = sm + s * STG_F;
        const float* Bs = As + A_ST_F;

        CP_WAIT1();
        __syncthreads();

#pragma unroll
        for (int kk = 0; kk < 2; kk++) {
            const int k = kk * 8;
            float af[4][4];
#pragma unroll
            for (int mt = 0; mt < 4; mt++) {
                int mb = wm + mt * 16;
                af[mt][0] = As[(mb + lr) * ASTR + k + lc];
                af[mt][1] = As[(mb + lr + 8) * ASTR + k + lc];
                af[mt][2] = As[(mb + lr) * ASTR + k + lc + 4];
                af[mt][3] = As[(mb + lr + 8) * ASTR + k + lc + 4];
            }
            float bf[4][2];
#pragma unroll
            for (int nt = 0; nt < 4; nt++) {
                int n = wn + nt * 8 + lr;
                bf[nt][0] = Bs[(k + lc) * BSTR + n];
                bf[nt][1] = Bs[(k + lc + 4) * BSTR + n];
            }
#pragma unroll
            for (int mt = 0; mt < 4; mt++)
#pragma unroll
                for (int nt = 0; nt < 4; nt++)
                    mma_tf32(acc[mt][nt], af[mt], bf[nt][0], bf[nt][1]);
        }
        __syncthreads();

        if (kc + 2 < K / 16) load_chunk((kc + 2) * 16, s);
        else CP_COMMIT();
    }

    // Epilogue
#pragma unroll
    for (int nt = 0; nt < 4; nt++) {
        int c = colBase + wn + nt * 8 + 2 * lc;
        float2 bv = *(const float2*)&bias[c];
#pragma unroll
        for (int mt = 0; mt < 4; mt++) {
            int r0 = rowBase + wm + mt * 16 + lr;
            int r1 = r0 + 8;
            float v00 = acc[mt][nt][0] + bv.x, v01 = acc[mt][nt][1] + bv.y;
            float v10 = acc[mt][nt][2] + bv.x, v11 = acc[mt][nt][3] + bv.y;
            if (MODE == 0) {
                int which = c >> 10;
                int c2    = c & 1023;
                int head  = c2 >> 6;
                int d     = c2 & 63;
                if (which == 0) {
                    float* dq = g_q + ((size_t)head * SEQ) * HD + d;
                    *(float2*)&dq[(size_t)r0 * HD] =
                        make_float2(tf32_rna(v00 * 0.125f), tf32_rna(v01 * 0.125f));
                    *(float2*)&dq[(size_t)r1 * HD] =
                        make_float2(tf32_rna(v10 * 0.125f), tf32_rna(v11 * 0.125f));
                } else {
                    float* dst = ((which == 1) ? g_k : g_v) + ((size_t)head * SEQ) * HD + d;
                    *(float2*)&dst[(size_t)r0 * HD] =
                        make_float2(tf32_rna(v00), tf32_rna(v01));
                    *(float2*)&dst[(size_t)r1 * HD] =
                        make_float2(tf32_rna(v10), tf32_rna(v11));
                }
            } else {
                *(float2*)&C[(size_t)r0 * N_ + c] = make_float2(v00, v01);
                *(float2*)&C[(size_t)r1 * N_ + c] = make_float2(v10, v11);
            }
        }
    }
}

// ---------------------------------------------------------------------------
// Warp-MMA tf32 flash attention. l fused into PV MMA via constant ones-column
// n-tile (accl): l = corr*l + sum(P) maintained by the tensor core, perfectly
// consistent with O's truncated-P accumulation. P stored raw (no CVT).
// ---------------------------------------------------------------------------
#define PSTR 68
#define KV_STAGE_F 8704
#define PS_OFF_F   17408

__global__ __launch_bounds__(128, 2) void attn_mma() {
    extern __shared__ float sm[];
    const uint32_t sb = smem_u32(sm);
    float* Ps = sm + PS_OFF_F;

    const int t    = threadIdx.x;
    const int w    = t >> 5;
    const int lane = t & 31;
    const int lr   = lane >> 2;
    const int lc   = lane & 3;
    const int w16  = w * 16;
    const int h  = blockIdx.y;
    const int qt = blockIdx.x;

    const float* Kh = g_k + (size_t)h * SEQ * HD;
    const float* Vh = g_v + (size_t)h * SEQ * HD;

    auto load_stage = [&](int kt2, int s) {
#pragma unroll
        for (int i = 0; i < 16; i++) {
            int id   = t + i * 128;
            int tile = id >> 10;
            int r    = (id >> 4) & 63;
            int c4   = id & 15;
            uint32_t dst = sb + (uint32_t)s * (KV_STAGE_F * 4)
                              + (uint32_t)tile * (64 * PSTR * 4)
                              + (uint32_t)r * (PSTR * 4) + (uint32_t)c4 * 16;
            const float* src = (tile ? Vh : Kh) + ((size_t)kt2 * 64 + r) * HD + c4 * 4;
            cp16(dst, src);
        }
        CP_COMMIT();
    };

    load_stage(0, 0);
    load_stage(1, 1);

    {
        const float* Qg = g_q + ((size_t)h * SEQ + (size_t)qt * 64) * HD;
#pragma unroll
        for (int i = 0; i < 8; i++) {
            int id = t + i * 128;
            int r  = id >> 4;
            int c  = (id & 15) * 4;
            *(float4*)&Ps[r * PSTR + c] = *(const float4*)&Qg[r * HD + c];
        }
    }
    __syncthreads();
    float qf[8][4];
#pragma unroll
    for (int k = 0; k < 8; k++) {
        qf[k][0] = Ps[(w16 + lr) * PSTR + k * 8 + lc];
        qf[k][1] = Ps[(w16 + lr + 8) * PSTR + k * 8 + lc];
        qf[k][2] = Ps[(w16 + lr) * PSTR + k * 8 + lc + 4];
        qf[k][3] = Ps[(w16 + lr + 8) * PSTR + k * 8 + lc + 4];
    }
    __syncthreads();

    float ob[8][4];
#pragma unroll
    for (int j = 0; j < 8; j++)
#pragma unroll
        for (int i = 0; i < 4; i++) ob[j][i] = 0.f;
    float accl[4] = {0.f, 0.f, 0.f, 0.f};          // ones-column accumulator (l)
    const float bl = (lr == 0) ? 1.f : 0.f;        // constant B-fragment of ones col
    float m0 = -1e30f, m1 = -1e30f;

    for (int kt = 0; kt < SEQ / 64; kt++) {
        const int s = kt & 1;
        const float* Ks = sm + s * KV_STAGE_F;
        const float* Vs = Ks + 64 * PSTR;

        CP_WAIT1();
        __syncthreads();

        // ---- S = Q * K^T ----
        float sc[8][4];
#pragma unroll
        for (int j = 0; j < 8; j++)
#pragma unroll
            for (int i = 0; i < 4; i++) sc[j][i] = 0.f;
#pragma unroll
        for (int k = 0; k < 8; k++) {
#pragma unroll
            for (int j = 0; j < 8; j++) {
                float b0 = Ks[(j * 8 + lr) * PSTR + k * 8 + lc];
                float b1 = Ks[(j * 8 + lr) * PSTR + k * 8 + lc + 4];
                mma_tf32(sc[j], qf[k], b0, b1);
            }
        }

        // ---- online softmax: max + exp; P stored raw (no cvt, no l sum) ----
        float mx0 = sc[0][0], mx1 = sc[0][2];
#pragma unroll
        for (int j = 0; j < 8; j++) {
            mx0 = fmaxf(mx0, fmaxf(sc[j][0], sc[j][1]));
            mx1 = fmaxf(mx1, fmaxf(sc[j][2], sc[j][3]));
        }
        mx0 = fmaxf(mx0, __shfl_xor_sync(0xffffffffu, mx0, 1));
        mx0 = fmaxf(mx0, __shfl_xor_sync(0xffffffffu, mx0, 2));
        mx1 = fmaxf(mx1, __shfl_xor_sync(0xffffffffu, mx1, 1));
        mx1 = fmaxf(mx1, __shfl_xor_sync(0xffffffffu, mx1, 2));
        float nm0 = fmaxf(m0, mx0), nm1 = fmaxf(m1, mx1);
        float corr0 = ex2f((m0 - nm0) * LOG2E);
        float corr1 = ex2f((m1 - nm1) * LOG2E);
#pragma unroll
        for (int j = 0; j < 8; j++) {
            float p00 = ex2f((sc[j][0] - nm0) * LOG2E);
            float p01 = ex2f((sc[j][1] - nm0) * LOG2E);
            float p10 = ex2f((sc[j][2] - nm1) * LOG2E);
            float p11 = ex2f((sc[j][3] - nm1) * LOG2E);
            *(float2*)&Ps[(w16 + lr) * PSTR + j * 8 + lc * 2]     = make_float2(p00, p01);
            *(float2*)&Ps[(w16 + lr + 8) * PSTR + j * 8 + lc * 2] = make_float2(p10, p11);
        }
        m0 = nm0; m1 = nm1;
#pragma unroll
        for (int j = 0; j < 8; j++) {
            ob[j][0] *= corr0; ob[j][1] *= corr0;
            ob[j][2] *= corr1; ob[j][3] *= corr1;
        }
        accl[0] *= corr0; accl[2] *= corr1;
        __syncthreads();

        // ---- O += P*V ; l += P*1 (ones column, constant B) ----
#pragma unroll
        for (int k = 0; k < 8; k++) {
            float pf[4];
            pf[0] = Ps[(w16 + lr) * PSTR + k * 8 + lc];
            pf[1] = Ps[(w16 + lr + 8) * PSTR + k * 8 + lc];
            pf[2] = Ps[(w16 + lr) * PSTR + k * 8 + lc + 4];
            pf[3] = Ps[(w16 + lr + 8) * PSTR + k * 8 + lc + 4];
#pragma unroll
            for (int j = 0; j < 8; j++) {
                float b0 = Vs[(k * 8 + lc) * PSTR + j * 8 + lr];
                float b1 = Vs[(k * 8 + lc + 4) * PSTR + j * 8 + lr];
                mma_tf32(ob[j], pf, b0, b1);
            }
            mma_tf32(accl, pf, bl, bl);
        }
        __syncthreads();

        if (kt + 2 < SEQ / 64) load_stage(kt + 2, s);
        else CP_COMMIT();
    }

    // l lives in lanes lc==0 (col 0 of ones-tile): broadcast within quad
    float l0 = __shfl_sync(0xffffffffu, accl[0], lane & 28);
    float l1 = __shfl_sync(0xffffffffu, accl[2], lane & 28);
    float inv0 = 1.f / l0, inv1 = 1.f / l1;
    float* d0 = g_att + ((size_t)qt * 64 + w16 + lr) * DIM + h * HD;
    float* d1 = d0 + 8 * DIM;
#pragma unroll
    for (int j = 0; j < 8; j++) {
        *(float2*)&d0[j * 8 + lc * 2] =
            make_float2(tf32_rna(ob[j][0] * inv0), tf32_rna(ob[j][1] * inv0));
        *(float2*)&d1[j * 8 + lc * 2] =
            make_float2(tf32_rna(ob[j][2] * inv1), tf32_rna(ob[j][3] * inv1));
    }
}

// ---------------------------------------------------------------------------
extern "C" void kernel_launch(void* const* d_in, const int* in_sizes, int n_in,
                              void* d_out, int out_size) {
    const float* x     = (const float*)d_in[0];
    const float* Wqkv  = (const float*)d_in[1];
    const float* bqkv  = (const float*)d_in[2];
    const float* Wproj = (const float*)d_in[3];
    const float* bproj = (const float*)d_in[4];
    float* out = (float*)d_out;

    const int gemm_shm = 2 * STG_F * (int)sizeof(float);
    const int attn_shm = (2 * KV_STAGE_F + 64 * PSTR) * (int)sizeof(float);

    // 0) pre-round x / W_qkv / W_proj to tf32
    pre_round<<<(int)((TOT4 + 255) / 256), 256>>>(x, Wqkv, Wproj);

    // 1) QKV projection (tf32 MMA, CVT-free)
    cudaFuncSetAttribute(gemm_tc<3 * DIM, 0>, cudaFuncAttributeMaxDynamicSharedMemorySize, gemm_shm);
    gemm_tc<3 * DIM, 0><<<dim3(24, 32), 256, gemm_shm>>>(bqkv, nullptr);

    // 2) warp-MMA tf32 flash attention (l fused into MMA)
    cudaFuncSetAttribute(attn_mma, cudaFuncAttributeMaxDynamicSharedMemorySize, attn_shm);
    attn_mma<<<dim3(SEQ / 64, NH), 128, attn_shm>>>();

    // 3) Output projection (tf32 MMA, CVT-free)
    cudaFuncSetAttribute(gemm_tc<DIM, 1>, cudaFuncAttributeMaxDynamicSharedMemorySize, gemm_shm);
    gemm_tc<DIM, 1><<<dim3(8, 32), 256, gemm_shm>>>(bproj, out);
}

// round 7
// speedup vs baseline: 9.1333x; 1.2410x over previous
#include <cuda_runtime.h>
#include <cstdint>

#define SEQ  4096
#define DIM  1024
#define NH   16
#define HD   64

// Scratch (allocation-free rule: __device__ globals)
__device__ float g_q[(size_t)NH * SEQ * HD];   // [H][SEQ][HD] tf32, pre-scaled 0.125
__device__ float g_k[(size_t)NH * SEQ * HD];   // [H][SEQ][HD] tf32
__device__ float g_v[(size_t)NH * HD * SEQ];   // [H][HD][SEQ] tf32 (d-major!)
__device__ float g_att[(size_t)SEQ * DIM];     // tf32 (attn epilogue)
__device__ float g_x [(size_t)SEQ * DIM];
__device__ float g_wq[(size_t)DIM * 3 * DIM];
__device__ float g_wp[(size_t)DIM * DIM];

// ---------------------------------------------------------------------------
__device__ __forceinline__ uint32_t smem_u32(const void* p) {
    uint32_t a;
    asm("{ .reg .u64 t; cvta.to.shared.u64 t, %1; cvt.u32.u64 %0, t; }" : "=r"(a) : "l"(p));
    return a;
}
__device__ __forceinline__ float ex2f(float x) {
    float r; asm("ex2.approx.ftz.f32 %0, %1;" : "=f"(r) : "f"(x)); return r;
}
__device__ __forceinline__ float tf32_rna(float x) {
    uint32_t u; asm("cvt.rna.tf32.f32 %0, %1;" : "=r"(u) : "f"(x)); return __uint_as_float(u);
}
__device__ __forceinline__ void cp16(uint32_t dst, const void* src) {
    asm volatile("cp.async.cg.shared.global [%0], [%1], 16;" :: "r"(dst), "l"(src));
}
#define CP_COMMIT() asm volatile("cp.async.commit_group;" ::: "memory")
#define CP_WAIT1()  asm volatile("cp.async.wait_group 1;" ::: "memory")

__device__ __forceinline__ void mma_tf32(float* d, const float* a, float b0, float b1) {
    asm volatile(
        "mma.sync.aligned.m16n8k8.row.col.f32.tf32.tf32.f32 "
        "{%0,%1,%2,%3}, {%4,%5,%6,%7}, {%8,%9}, {%0,%1,%2,%3};"
        : "+f"(d[0]), "+f"(d[1]), "+f"(d[2]), "+f"(d[3])
        : "r"(__float_as_uint(a[0])), "r"(__float_as_uint(a[1])),
          "r"(__float_as_uint(a[2])), "r"(__float_as_uint(a[3])),
          "r"(__float_as_uint(b0)), "r"(__float_as_uint(b1)));
}

#define LOG2E 1.44269504f

// ---------------------------------------------------------------------------
// Pre-round x / W_qkv / W_proj to tf32 (RNA) once per launch.
// ---------------------------------------------------------------------------
#define XN   ((size_t)SEQ * DIM)
#define WQN  ((size_t)DIM * 3 * DIM)
#define WPN  ((size_t)DIM * DIM)
#define TOT4 ((XN + WQN + WPN) / 4)

__global__ __launch_bounds__(256) void pre_round(const float* __restrict__ x,
                                                 const float* __restrict__ wq,
                                                 const float* __restrict__ wp) {
    size_t i = (size_t)blockIdx.x * blockDim.x + threadIdx.x;
    if (i >= TOT4) return;
    const float* src;
    float* dst;
    size_t off;
    if (i < XN / 4)                { src = x;  dst = g_x;  off = i; }
    else if (i < (XN + WQN) / 4)   { src = wq; dst = g_wq; off = i - XN / 4; }
    else                           { src = wp; dst = g_wp; off = i - (XN + WQN) / 4; }
    float4 v = ((const float4*)src)[off];
    v.x = tf32_rna(v.x); v.y = tf32_rna(v.y);
    v.z = tf32_rna(v.z); v.w = tf32_rna(v.w);
    ((float4*)dst)[off] = v;
}

// ---------------------------------------------------------------------------
// tf32 warp-MMA GEMM. k-slot permutation: slot (g,lc)->phys 8g+2lc,
// (g,lc+4)->phys 8g+2lc+1. A-frags become float2 loads (ASTR=24, conflict-
// free); B rows remapped at cp.async time so B reads stay natural+conflict-free.
// MODE 0: A=g_x,B=g_wq, scatter q(x0.125)/k/v (v d-major). MODE 1: g_att x g_wp.
// ---------------------------------------------------------------------------
#define ASTR 24
#define BSTR 136
#define A_ST_F (128 * ASTR)            // 3072
#define B_ST_F (16 * BSTR)             // 2176
#define STG_F  (A_ST_F + B_ST_F)       // 5248

template <int N_, int MODE>
__global__ __launch_bounds__(256) void gemm_tc(const float* __restrict__ bias,
                                               float* __restrict__ C) {
    extern __shared__ float sm[];
    const uint32_t sb = smem_u32(sm);
    const int K = DIM;
    const float* A = (MODE == 1) ? g_att : g_x;
    const float* B = (MODE == 1) ? g_wp : g_wq;

    const int t    = threadIdx.x;
    const int w    = t >> 5;
    const int lane = t & 31;
    const int lr   = lane >> 2;
    const int lc   = lane & 3;
    const int wm   = (w >> 2) * 64;
    const int wn   = (w & 3) * 32;
    const int rowBase = blockIdx.y * 128;
    const int colBase = blockIdx.x * 128;

    auto load_chunk = [&](int k0, int s) {
        uint32_t base = sb + (uint32_t)s * (STG_F * 4);
#pragma unroll
        for (int i = 0; i < 2; i++) {           // A: 128 rows x 4 float4
            int id = t + i * 256;
            int r  = id >> 2;
            int c4 = id & 3;
            cp16(base + (uint32_t)r * (ASTR * 4) + (uint32_t)c4 * 16,
                 A + (size_t)(rowBase + r) * K + k0 + c4 * 4);
        }
#pragma unroll
        for (int i = 0; i < 2; i++) {           // B: 16 rows x 32 float4, row remap
            int id = t + i * 256;
            int r  = id >> 5;                   // phys row in chunk
            int c4 = id & 31;
            int j  = r & 7;
            int rs = (r & 8) + ((j & 1) ? (j >> 1) + 4 : (j >> 1));
            cp16(base + (uint32_t)(A_ST_F * 4) + (uint32_t)rs * (BSTR * 4) + (uint32_t)c4 * 16,
                 B + (size_t)(k0 + r) * N_ + colBase + c4 * 4);
        }
        CP_COMMIT();
    };

    load_chunk(0, 0);
    load_chunk(16, 1);

    float acc[4][4][4];
#pragma unroll
    for (int mt = 0; mt < 4; mt++)
#pragma unroll
        for (int nt = 0; nt < 4; nt++)
#pragma unroll
            for (int i = 0; i < 4; i++) acc[mt][nt][i] = 0.f;

    for (int kc = 0; kc < K / 16; kc++) {
        const int s = kc & 1;
        const float* As = sm + s * STG_F;
        const float* Bs = As + A_ST_F;

        CP_WAIT1();
        __syncthreads();

#pragma unroll
        for (int kk = 0; kk < 2; kk++) {
            const int k = kk * 8;
            float af[4][4];
#pragma unroll
            for (int mt = 0; mt < 4; mt++) {
                int mb = wm + mt * 16;
                float2 a0 = *(const float2*)&As[(mb + lr) * ASTR + k + 2 * lc];
                float2 a1 = *(const float2*)&As[(mb + lr + 8) * ASTR + k + 2 * lc];
                af[mt][0] = a0.x; af[mt][2] = a0.y;
                af[mt][1] = a1.x; af[mt][3] = a1.y;
            }
            float bf[4][2];
#pragma unroll
            for (int nt = 0; nt < 4; nt++) {
                int n = wn + nt * 8 + lr;
                bf[nt][0] = Bs[(k + lc) * BSTR + n];
                bf[nt][1] = Bs[(k + lc + 4) * BSTR + n];
            }
#pragma unroll
            for (int mt = 0; mt < 4; mt++)
#pragma unroll
                for (int nt = 0; nt < 4; nt++)
                    mma_tf32(acc[mt][nt], af[mt], bf[nt][0], bf[nt][1]);
        }
        __syncthreads();

        if (kc + 2 < K / 16) load_chunk((kc + 2) * 16, s);
        else CP_COMMIT();
    }

    // Epilogue
#pragma unroll
    for (int nt = 0; nt < 4; nt++) {
        int c = colBase + wn + nt * 8 + 2 * lc;
        float2 bv = *(const float2*)&bias[c];
#pragma unroll
        for (int mt = 0; mt < 4; mt++) {
            int r0 = rowBase + wm + mt * 16 + lr;
            int r1 = r0 + 8;
            float v00 = acc[mt][nt][0] + bv.x, v01 = acc[mt][nt][1] + bv.y;
            float v10 = acc[mt][nt][2] + bv.x, v11 = acc[mt][nt][3] + bv.y;
            if (MODE == 0) {
                int which = c >> 10;
                int c2    = c & 1023;
                int head  = c2 >> 6;
                int d     = c2 & 63;
                if (which == 0) {
                    float* dq = g_q + ((size_t)head * SEQ) * HD + d;
                    *(float2*)&dq[(size_t)r0 * HD] =
                        make_float2(tf32_rna(v00 * 0.125f), tf32_rna(v01 * 0.125f));
                    *(float2*)&dq[(size_t)r1 * HD] =
                        make_float2(tf32_rna(v10 * 0.125f), tf32_rna(v11 * 0.125f));
                } else if (which == 1) {
                    float* dk = g_k + ((size_t)head * SEQ) * HD + d;
                    *(float2*)&dk[(size_t)r0 * HD] = make_float2(tf32_rna(v00), tf32_rna(v01));
                    *(float2*)&dk[(size_t)r1 * HD] = make_float2(tf32_rna(v10), tf32_rna(v11));
                } else {
                    // v: d-major [H][HD][SEQ]
                    float* dv = g_v + (size_t)head * HD * SEQ;
                    dv[(size_t)(d)     * SEQ + r0] = tf32_rna(v00);
                    dv[(size_t)(d + 1) * SEQ + r0] = tf32_rna(v01);
                    dv[(size_t)(d)     * SEQ + r1] = tf32_rna(v10);
                    dv[(size_t)(d + 1) * SEQ + r1] = tf32_rna(v11);
                }
            } else {
                *(float2*)&C[(size_t)r0 * N_ + c] = make_float2(v00, v01);
                *(float2*)&C[(size_t)r1 * N_ + c] = make_float2(v10, v11);
            }
        }
    }
}

// ---------------------------------------------------------------------------
// Warp-MMA tf32 flash attention with k-slot permutation -> all fragment smem
// traffic is float2 (LDS.64), conflict-free at stride 72.
// K tile: [64 key][72] (cols=d). V tile: [64 d][72] (cols=key, from d-major g_v).
// Ps: [64][72] P/Q staging. l fused into PV via ones-column MMA.
// ---------------------------------------------------------------------------
#define PSTR 72
#define KV_STAGE_F (2 * 64 * PSTR)     // 9216 floats (K + V)
#define PS_OFF_F   (2 * KV_STAGE_F)    // 18432
#define ATTN_SM_F  (PS_OFF_F + 64 * PSTR)   // 23040 floats = 92160 B

__global__ __launch_bounds__(128, 2) void attn_mma() {
    extern __shared__ float sm[];
    const uint32_t sb = smem_u32(sm);
    float* Ps = sm + PS_OFF_F;

    const int t    = threadIdx.x;
    const int w    = t >> 5;
    const int lane = t & 31;
    const int lr   = lane >> 2;
    const int lc   = lane & 3;
    const int w16  = w * 16;
    const int h  = blockIdx.y;
    const int qt = blockIdx.x;

    const float* Kh = g_k + (size_t)h * SEQ * HD;   // [key][d]
    const float* Vh = g_v + (size_t)h * HD * SEQ;   // [d][key]

    auto load_stage = [&](int kt2, int s) {
#pragma unroll
        for (int i = 0; i < 16; i++) {
            int id   = t + i * 128;            // 0..2047
            int tile = id >> 10;               // 0=K 1=V
            int r    = (id >> 4) & 63;
            int c4   = id & 15;
            uint32_t dst = sb + (uint32_t)s * (KV_STAGE_F * 4)
                              + (uint32_t)tile * (64 * PSTR * 4)
                              + (uint32_t)r * (PSTR * 4) + (uint32_t)c4 * 16;
            const float* src = tile
                ? Vh + (size_t)r * SEQ + (size_t)kt2 * 64 + c4 * 4     // r = d
                : Kh + ((size_t)kt2 * 64 + r) * HD + c4 * 4;           // r = key
            cp16(dst, src);
        }
        CP_COMMIT();
    };

    load_stage(0, 0);
    load_stage(1, 1);

    // Stage Q through Ps, build permuted-slot fragments (float2)
    {
        const float* Qg = g_q + ((size_t)h * SEQ + (size_t)qt * 64) * HD;
#pragma unroll
        for (int i = 0; i < 8; i++) {
            int id = t + i * 128;
            int r  = id >> 4;
            int c  = (id & 15) * 4;
            *(float4*)&Ps[r * PSTR + c] = *(const float4*)&Qg[r * HD + c];
        }
    }
    __syncthreads();
    float qf[8][4];
#pragma unroll
    for (int k = 0; k < 8; k++) {
        float2 a0 = *(const float2*)&Ps[(w16 + lr) * PSTR + k * 8 + 2 * lc];
        float2 a1 = *(const float2*)&Ps[(w16 + lr + 8) * PSTR + k * 8 + 2 * lc];
        qf[k][0] = a0.x; qf[k][2] = a0.y;
        qf[k][1] = a1.x; qf[k][3] = a1.y;
    }
    __syncthreads();

    float ob[8][4];
#pragma unroll
    for (int j = 0; j < 8; j++)
#pragma unroll
        for (int i = 0; i < 4; i++) ob[j][i] = 0.f;
    float accl[4] = {0.f, 0.f, 0.f, 0.f};
    const float bl = (lr == 0) ? 1.f : 0.f;
    float m0 = -1e30f, m1 = -1e30f;

    for (int kt = 0; kt < SEQ / 64; kt++) {
        const int s = kt & 1;
        const float* Ks = sm + s * KV_STAGE_F;
        const float* Vs = Ks + 64 * PSTR;

        CP_WAIT1();
        __syncthreads();

        // ---- S = Q * K^T (B reads: float2, permuted k-slots) ----
        float sc[8][4];
#pragma unroll
        for (int j = 0; j < 8; j++)
#pragma unroll
            for (int i = 0; i < 4; i++) sc[j][i] = 0.f;
#pragma unroll
        for (int k = 0; k < 8; k++) {
#pragma unroll
            for (int j = 0; j < 8; j++) {
                float2 b = *(const float2*)&Ks[(j * 8 + lr) * PSTR + k * 8 + 2 * lc];
                mma_tf32(sc[j], qf[k], b.x, b.y);
            }
        }

        // ---- online softmax; P stored raw as float2 pairs ----
        float mx0 = sc[0][0], mx1 = sc[0][2];
#pragma unroll
        for (int j = 0; j < 8; j++) {
            mx0 = fmaxf(mx0, fmaxf(sc[j][0], sc[j][1]));
            mx1 = fmaxf(mx1, fmaxf(sc[j][2], sc[j][3]));
        }
        mx0 = fmaxf(mx0, __shfl_xor_sync(0xffffffffu, mx0, 1));
        mx0 = fmaxf(mx0, __shfl_xor_sync(0xffffffffu, mx0, 2));
        mx1 = fmaxf(mx1, __shfl_xor_sync(0xffffffffu, mx1, 1));
        mx1 = fmaxf(mx1, __shfl_xor_sync(0xffffffffu, mx1, 2));
        float nm0 = fmaxf(m0, mx0), nm1 = fmaxf(m1, mx1);
        float corr0 = ex2f((m0 - nm0) * LOG2E);
        float corr1 = ex2f((m1 - nm1) * LOG2E);
#pragma unroll
        for (int j = 0; j < 8; j++) {
            float p00 = ex2f((sc[j][0] - nm0) * LOG2E);
            float p01 = ex2f((sc[j][1] - nm0) * LOG2E);
            float p10 = ex2f((sc[j][2] - nm1) * LOG2E);
            float p11 = ex2f((sc[j][3] - nm1) * LOG2E);
            *(float2*)&Ps[(w16 + lr) * PSTR + j * 8 + lc * 2]     = make_float2(p00, p01);
            *(float2*)&Ps[(w16 + lr + 8) * PSTR + j * 8 + lc * 2] = make_float2(p10, p11);
        }
        m0 = nm0; m1 = nm1;
#pragma unroll
        for (int j = 0; j < 8; j++) {
            ob[j][0] *= corr0; ob[j][1] *= corr0;
            ob[j][2] *= corr1; ob[j][3] *= corr1;
        }
        accl[0] *= corr0; accl[2] *= corr1;
        __syncthreads();

        // ---- O += P*V ; l += P*1 (all fragment reads float2) ----
#pragma unroll
        for (int k = 0; k < 8; k++) {
            float pf[4];
            {
                float2 f0 = *(const float2*)&Ps[(w16 + lr) * PSTR + k * 8 + 2 * lc];
                float2 f1 = *(const float2*)&Ps[(w16 + lr + 8) * PSTR + k * 8 + 2 * lc];
                pf[0] = f0.x; pf[2] = f0.y;
                pf[1] = f1.x; pf[3] = f1.y;
            }
#pragma unroll
            for (int j = 0; j < 8; j++) {
                float2 b = *(const float2*)&Vs[(j * 8 + lr) * PSTR + k * 8 + 2 * lc];
                mma_tf32(ob[j], pf, b.x, b.y);
            }
            mma_tf32(accl, pf, bl, bl);
        }
        __syncthreads();

        if (kt + 2 < SEQ / 64) load_stage(kt + 2, s);
        else CP_COMMIT();
    }

    float l0 = __shfl_sync(0xffffffffu, accl[0], lane & 28);
    float l1 = __shfl_sync(0xffffffffu, accl[2], lane & 28);
    float inv0 = 1.f / l0, inv1 = 1.f / l1;
    float* d0 = g_att + ((size_t)qt * 64 + w16 + lr) * DIM + h * HD;
    float* d1 = d0 + 8 * DIM;
#pragma unroll
    for (int j = 0; j < 8; j++) {
        *(float2*)&d0[j * 8 + lc * 2] =
            make_float2(tf32_rna(ob[j][0] * inv0), tf32_rna(ob[j][1] * inv0));
        *(float2*)&d1[j * 8 + lc * 2] =
            make_float2(tf32_rna(ob[j][2] * inv1), tf32_rna(ob[j][3] * inv1));
    }
}

// ---------------------------------------------------------------------------
extern "C" void kernel_launch(void* const* d_in, const int* in_sizes, int n_in,
                              void* d_out, int out_size) {
    const float* x     = (const float*)d_in[0];
    const float* Wqkv  = (const float*)d_in[1];
    const float* bqkv  = (const float*)d_in[2];
    const float* Wproj = (const float*)d_in[3];
    const float* bproj = (const float*)d_in[4];
    float* out = (float*)d_out;

    const int gemm_shm = 2 * STG_F * (int)sizeof(float);        // 41984 B
    const int attn_shm = ATTN_SM_F * (int)sizeof(float);        // 92160 B

    // 0) pre-round x / W_qkv / W_proj to tf32
    pre_round<<<(int)((TOT4 + 255) / 256), 256>>>(x, Wqkv, Wproj);

    // 1) QKV projection (tf32 MMA) -> q (scaled), k [H,SEQ,HD], v [H,HD,SEQ]
    cudaFuncSetAttribute(gemm_tc<3 * DIM, 0>, cudaFuncAttributeMaxDynamicSharedMemorySize, gemm_shm);
    gemm_tc<3 * DIM, 0><<<dim3(24, 32), 256, gemm_shm>>>(bqkv, nullptr);

    // 2) warp-MMA tf32 flash attention (float2 fragment traffic)
    cudaFuncSetAttribute(attn_mma, cudaFuncAttributeMaxDynamicSharedMemorySize, attn_shm);
    attn_mma<<<dim3(SEQ / 64, NH), 128, attn_shm>>>();

    // 3) Output projection (tf32 MMA)
    cudaFuncSetAttribute(gemm_tc<DIM, 1>, cudaFuncAttributeMaxDynamicSharedMemorySize, gemm_shm);
    gemm_tc<DIM, 1><<<dim3(8, 32), 256, gemm_shm>>>(bproj, out);
}

// round 8
// speedup vs baseline: 9.9469x; 1.0891x over previous
#include <cuda_runtime.h>
#include <cstdint>

#define SEQ  4096
#define DIM  1024
#define NH   16
#define HD   64

// Scratch (allocation-free rule: __device__ globals)
__device__ float g_q[(size_t)NH * SEQ * HD];   // [H][SEQ][HD] tf32, pre-scaled 0.125
__device__ float g_k[(size_t)NH * SEQ * HD];   // [H][SEQ][HD] tf32
__device__ float g_v[(size_t)NH * HD * SEQ];   // [H][HD][SEQ] tf32 (d-major!)
__device__ float g_att[(size_t)SEQ * DIM];     // tf32 (attn epilogue)
__device__ float g_x [(size_t)SEQ * DIM];
__device__ float g_wq[(size_t)DIM * 3 * DIM];
__device__ float g_wp[(size_t)DIM * DIM];

// ---------------------------------------------------------------------------
__device__ __forceinline__ uint32_t smem_u32(const void* p) {
    uint32_t a;
    asm("{ .reg .u64 t; cvta.to.shared.u64 t, %1; cvt.u32.u64 %0, t; }" : "=r"(a) : "l"(p));
    return a;
}
__device__ __forceinline__ float ex2f(float x) {
    float r; asm("ex2.approx.ftz.f32 %0, %1;" : "=f"(r) : "f"(x)); return r;
}
__device__ __forceinline__ float tf32_rna(float x) {
    uint32_t u; asm("cvt.rna.tf32.f32 %0, %1;" : "=r"(u) : "f"(x)); return __uint_as_float(u);
}
__device__ __forceinline__ void cp16(uint32_t dst, const void* src) {
    asm volatile("cp.async.cg.shared.global [%0], [%1], 16;" :: "r"(dst), "l"(src));
}
#define CP_COMMIT() asm volatile("cp.async.commit_group;" ::: "memory")
#define CP_WAIT1()  asm volatile("cp.async.wait_group 1;" ::: "memory")

__device__ __forceinline__ void mma_tf32(float* d, const float* a, float b0, float b1) {
    asm volatile(
        "mma.sync.aligned.m16n8k8.row.col.f32.tf32.tf32.f32 "
        "{%0,%1,%2,%3}, {%4,%5,%6,%7}, {%8,%9}, {%0,%1,%2,%3};"
        : "+f"(d[0]), "+f"(d[1]), "+f"(d[2]), "+f"(d[3])
        : "r"(__float_as_uint(a[0])), "r"(__float_as_uint(a[1])),
          "r"(__float_as_uint(a[2])), "r"(__float_as_uint(a[3])),
          "r"(__float_as_uint(b0)), "r"(__float_as_uint(b1)));
}

#define LOG2E 1.44269504f

// ---------------------------------------------------------------------------
// Pre-round x / W_qkv / W_proj to tf32 (RNA) once per launch.
// ---------------------------------------------------------------------------
#define XN   ((size_t)SEQ * DIM)
#define WQN  ((size_t)DIM * 3 * DIM)
#define WPN  ((size_t)DIM * DIM)
#define TOT4 ((XN + WQN + WPN) / 4)

__global__ __launch_bounds__(256) void pre_round(const float* __restrict__ x,
                                                 const float* __restrict__ wq,
                                                 const float* __restrict__ wp) {
    size_t i = (size_t)blockIdx.x * blockDim.x + threadIdx.x;
    if (i >= TOT4) return;
    const float* src;
    float* dst;
    size_t off;
    if (i < XN / 4)                { src = x;  dst = g_x;  off = i; }
    else if (i < (XN + WQN) / 4)   { src = wq; dst = g_wq; off = i - XN / 4; }
    else                           { src = wp; dst = g_wp; off = i - (XN + WQN) / 4; }
    float4 v = ((const float4*)src)[off];
    v.x = tf32_rna(v.x); v.y = tf32_rna(v.y);
    v.z = tf32_rna(v.z); v.w = tf32_rna(v.w);
    ((float4*)dst)[off] = v;
}

// ---------------------------------------------------------------------------
// tf32 warp-MMA GEMM (unchanged from round 7).
// ---------------------------------------------------------------------------
#define ASTR 24
#define BSTR 136
#define A_ST_F (128 * ASTR)
#define B_ST_F (16 * BSTR)
#define STG_F  (A_ST_F + B_ST_F)

template <int N_, int MODE>
__global__ __launch_bounds__(256) void gemm_tc(const float* __restrict__ bias,
                                               float* __restrict__ C) {
    extern __shared__ float sm[];
    const uint32_t sb = smem_u32(sm);
    const int K = DIM;
    const float* A = (MODE == 1) ? g_att : g_x;
    const float* B = (MODE == 1) ? g_wp : g_wq;

    const int t    = threadIdx.x;
    const int w    = t >> 5;
    const int lane = t & 31;
    const int lr   = lane >> 2;
    const int lc   = lane & 3;
    const int wm   = (w >> 2) * 64;
    const int wn   = (w & 3) * 32;
    const int rowBase = blockIdx.y * 128;
    const int colBase = blockIdx.x * 128;

    auto load_chunk = [&](int k0, int s) {
        uint32_t base = sb + (uint32_t)s * (STG_F * 4);
#pragma unroll
        for (int i = 0; i < 2; i++) {
            int id = t + i * 256;
            int r  = id >> 2;
            int c4 = id & 3;
            cp16(base + (uint32_t)r * (ASTR * 4) + (uint32_t)c4 * 16,
                 A + (size_t)(rowBase + r) * K + k0 + c4 * 4);
        }
#pragma unroll
        for (int i = 0; i < 2; i++) {
            int id = t + i * 256;
            int r  = id >> 5;
            int c4 = id & 31;
            int j  = r & 7;
            int rs = (r & 8) + ((j & 1) ? (j >> 1) + 4 : (j >> 1));
            cp16(base + (uint32_t)(A_ST_F * 4) + (uint32_t)rs * (BSTR * 4) + (uint32_t)c4 * 16,
                 B + (size_t)(k0 + r) * N_ + colBase + c4 * 4);
        }
        CP_COMMIT();
    };

    load_chunk(0, 0);
    load_chunk(16, 1);

    float acc[4][4][4];
#pragma unroll
    for (int mt = 0; mt < 4; mt++)
#pragma unroll
        for (int nt = 0; nt < 4; nt++)
#pragma unroll
            for (int i = 0; i < 4; i++) acc[mt][nt][i] = 0.f;

    for (int kc = 0; kc < K / 16; kc++) {
        const int s = kc & 1;
        const float* As = sm + s * STG_F;
        const float* Bs = As + A_ST_F;

        CP_WAIT1();
        __syncthreads();

#pragma unroll
        for (int kk = 0; kk < 2; kk++) {
            const int k = kk * 8;
            float af[4][4];
#pragma unroll
            for (int mt = 0; mt < 4; mt++) {
                int mb = wm + mt * 16;
                float2 a0 = *(const float2*)&As[(mb + lr) * ASTR + k + 2 * lc];
                float2 a1 = *(const float2*)&As[(mb + lr + 8) * ASTR + k + 2 * lc];
                af[mt][0] = a0.x; af[mt][2] = a0.y;
                af[mt][1] = a1.x; af[mt][3] = a1.y;
            }
            float bf[4][2];
#pragma unroll
            for (int nt = 0; nt < 4; nt++) {
                int n = wn + nt * 8 + lr;
                bf[nt][0] = Bs[(k + lc) * BSTR + n];
                bf[nt][1] = Bs[(k + lc + 4) * BSTR + n];
            }
#pragma unroll
            for (int mt = 0; mt < 4; mt++)
#pragma unroll
                for (int nt = 0; nt < 4; nt++)
                    mma_tf32(acc[mt][nt], af[mt], bf[nt][0], bf[nt][1]);
        }
        __syncthreads();

        if (kc + 2 < K / 16) load_chunk((kc + 2) * 16, s);
        else CP_COMMIT();
    }

    // Epilogue
#pragma unroll
    for (int nt = 0; nt < 4; nt++) {
        int c = colBase + wn + nt * 8 + 2 * lc;
        float2 bv = *(const float2*)&bias[c];
#pragma unroll
        for (int mt = 0; mt < 4; mt++) {
            int r0 = rowBase + wm + mt * 16 + lr;
            int r1 = r0 + 8;
            float v00 = acc[mt][nt][0] + bv.x, v01 = acc[mt][nt][1] + bv.y;
            float v10 = acc[mt][nt][2] + bv.x, v11 = acc[mt][nt][3] + bv.y;
            if (MODE == 0) {
                int which = c >> 10;
                int c2    = c & 1023;
                int head  = c2 >> 6;
                int d     = c2 & 63;
                if (which == 0) {
                    float* dq = g_q + ((size_t)head * SEQ) * HD + d;
                    *(float2*)&dq[(size_t)r0 * HD] =
                        make_float2(tf32_rna(v00 * 0.125f), tf32_rna(v01 * 0.125f));
                    *(float2*)&dq[(size_t)r1 * HD] =
                        make_float2(tf32_rna(v10 * 0.125f), tf32_rna(v11 * 0.125f));
                } else if (which == 1) {
                    float* dk = g_k + ((size_t)head * SEQ) * HD + d;
                    *(float2*)&dk[(size_t)r0 * HD] = make_float2(tf32_rna(v00), tf32_rna(v01));
                    *(float2*)&dk[(size_t)r1 * HD] = make_float2(tf32_rna(v10), tf32_rna(v11));
                } else {
                    float* dv = g_v + (size_t)head * HD * SEQ;
                    dv[(size_t)(d)     * SEQ + r0] = tf32_rna(v00);
                    dv[(size_t)(d + 1) * SEQ + r0] = tf32_rna(v01);
                    dv[(size_t)(d)     * SEQ + r1] = tf32_rna(v10);
                    dv[(size_t)(d + 1) * SEQ + r1] = tf32_rna(v11);
                }
            } else {
                *(float2*)&C[(size_t)r0 * N_ + c] = make_float2(v00, v01);
                *(float2*)&C[(size_t)r1 * N_ + c] = make_float2(v10, v11);
            }
        }
    }
}

// ---------------------------------------------------------------------------
// Warp-MMA tf32 flash attention, P fully register-resident:
// S-accumulator frag == PV A-frag under the shared k-slot permutation, so
// P is never written to smem. 2 barriers/iter. l fused via ones-column MMA.
// K tile: [64 key][72] (cols=d). V tile: [64 d][72] (cols=key, d-major g_v).
// Qstage: [64][72], used once at startup.
// ---------------------------------------------------------------------------
#define PSTR 72
#define KV_STAGE_F (2 * 64 * PSTR)     // 9216 floats (K + V)
#define QS_OFF_F   (2 * KV_STAGE_F)    // 18432
#define ATTN_SM_F  (QS_OFF_F + 64 * PSTR)   // 23040 floats = 92160 B

__global__ __launch_bounds__(128, 2) void attn_mma() {
    extern __shared__ float sm[];
    const uint32_t sb = smem_u32(sm);
    float* Qs = sm + QS_OFF_F;

    const int t    = threadIdx.x;
    const int lane = t & 31;
    const int lr   = lane >> 2;
    const int lc   = lane & 3;
    const int w16  = (t >> 5) * 16;
    const int h  = blockIdx.y;
    const int qt = blockIdx.x;

    const float* Kh = g_k + (size_t)h * SEQ * HD;   // [key][d]
    const float* Vh = g_v + (size_t)h * HD * SEQ;   // [d][key]

    auto load_stage = [&](int kt2, int s) {
#pragma unroll
        for (int i = 0; i < 16; i++) {
            int id   = t + i * 128;            // 0..2047
            int tile = id >> 10;               // 0=K 1=V
            int r    = (id >> 4) & 63;
            int c4   = id & 15;
            uint32_t dst = sb + (uint32_t)s * (KV_STAGE_F * 4)
                              + (uint32_t)tile * (64 * PSTR * 4)
                              + (uint32_t)r * (PSTR * 4) + (uint32_t)c4 * 16;
            const float* src = tile
                ? Vh + (size_t)r * SEQ + (size_t)kt2 * 64 + c4 * 4     // r = d
                : Kh + ((size_t)kt2 * 64 + r) * HD + c4 * 4;           // r = key
            cp16(dst, src);
        }
        CP_COMMIT();
    };

    load_stage(0, 0);
    load_stage(1, 1);

    // Stage Q once, build permuted-slot fragments (float2)
    {
        const float* Qg = g_q + ((size_t)h * SEQ + (size_t)qt * 64) * HD;
#pragma unroll
        for (int i = 0; i < 8; i++) {
            int id = t + i * 128;
            int r  = id >> 4;
            int c  = (id & 15) * 4;
            *(float4*)&Qs[r * PSTR + c] = *(const float4*)&Qg[r * HD + c];
        }
    }
    __syncthreads();
    float qf[8][4];
#pragma unroll
    for (int k = 0; k < 8; k++) {
        float2 a0 = *(const float2*)&Qs[(w16 + lr) * PSTR + k * 8 + 2 * lc];
        float2 a1 = *(const float2*)&Qs[(w16 + lr + 8) * PSTR + k * 8 + 2 * lc];
        qf[k][0] = a0.x; qf[k][2] = a0.y;
        qf[k][1] = a1.x; qf[k][3] = a1.y;
    }
    // no barrier needed: Qs is never written again

    float ob[8][4];
#pragma unroll
    for (int j = 0; j < 8; j++)
#pragma unroll
        for (int i = 0; i < 4; i++) ob[j][i] = 0.f;
    float accl[4] = {0.f, 0.f, 0.f, 0.f};
    const float bl = (lr == 0) ? 1.f : 0.f;
    float m0 = -1e30f, m1 = -1e30f;

    for (int kt = 0; kt < SEQ / 64; kt++) {
        const int s = kt & 1;
        const float* Ks = sm + s * KV_STAGE_F;
        const float* Vs = Ks + 64 * PSTR;

        CP_WAIT1();
        __syncthreads();   // stage s ready

        // ---- S = Q * K^T ----
        float sc[8][4];
#pragma unroll
        for (int j = 0; j < 8; j++)
#pragma unroll
            for (int i = 0; i < 4; i++) sc[j][i] = 0.f;
#pragma unroll
        for (int k = 0; k < 8; k++) {
#pragma unroll
            for (int j = 0; j < 8; j++) {
                float2 b = *(const float2*)&Ks[(j * 8 + lr) * PSTR + k * 8 + 2 * lc];
                mma_tf32(sc[j], qf[k], b.x, b.y);
            }
        }

        // ---- online softmax, P stays in sc registers ----
        float mx0 = sc[0][0], mx1 = sc[0][2];
#pragma unroll
        for (int j = 0; j < 8; j++) {
            mx0 = fmaxf(mx0, fmaxf(sc[j][0], sc[j][1]));
            mx1 = fmaxf(mx1, fmaxf(sc[j][2], sc[j][3]));
        }
        mx0 = fmaxf(mx0, __shfl_xor_sync(0xffffffffu, mx0, 1));
        mx0 = fmaxf(mx0, __shfl_xor_sync(0xffffffffu, mx0, 2));
        mx1 = fmaxf(mx1, __shfl_xor_sync(0xffffffffu, mx1, 1));
        mx1 = fmaxf(mx1, __shfl_xor_sync(0xffffffffu, mx1, 2));
        float nm0 = fmaxf(m0, mx0), nm1 = fmaxf(m1, mx1);
        float corr0 = ex2f((m0 - nm0) * LOG2E);
        float corr1 = ex2f((m1 - nm1) * LOG2E);
#pragma unroll
        for (int j = 0; j < 8; j++) {
            sc[j][0] = ex2f((sc[j][0] - nm0) * LOG2E);
            sc[j][1] = ex2f((sc[j][1] - nm0) * LOG2E);
            sc[j][2] = ex2f((sc[j][2] - nm1) * LOG2E);
            sc[j][3] = ex2f((sc[j][3] - nm1) * LOG2E);
        }
        m0 = nm0; m1 = nm1;
#pragma unroll
        for (int j = 0; j < 8; j++) {
            ob[j][0] *= corr0; ob[j][1] *= corr0;
            ob[j][2] *= corr1; ob[j][3] *= corr1;
        }
        accl[0] *= corr0; accl[2] *= corr1;

        // ---- O += P*V ; l += P*1  (P fragments direct from sc registers) ----
#pragma unroll
        for (int k = 0; k < 8; k++) {
            float pf[4];
            pf[0] = sc[k][0];   // P[lr][key 8k+2lc]
            pf[1] = sc[k][2];   // P[lr+8][key 8k+2lc]
            pf[2] = sc[k][1];   // P[lr][key 8k+2lc+1]
            pf[3] = sc[k][3];   // P[lr+8][key 8k+2lc+1]
#pragma unroll
            for (int j = 0; j < 8; j++) {
                float2 b = *(const float2*)&Vs[(j * 8 + lr) * PSTR + k * 8 + 2 * lc];
                mma_tf32(ob[j], pf, b.x, b.y);
            }
            mma_tf32(accl, pf, bl, bl);
        }
        __syncthreads();   // stage s fully consumed by all warps

        if (kt + 2 < SEQ / 64) load_stage(kt + 2, s);
        else CP_COMMIT();
    }

    float l0 = __shfl_sync(0xffffffffu, accl[0], lane & 28);
    float l1 = __shfl_sync(0xffffffffu, accl[2], lane & 28);
    float inv0 = 1.f / l0, inv1 = 1.f / l1;
    float* d0 = g_att + ((size_t)qt * 64 + w16 + lr) * DIM + h * HD;
    float* d1 = d0 + 8 * DIM;
#pragma unroll
    for (int j = 0; j < 8; j++) {
        *(float2*)&d0[j * 8 + lc * 2] =
            make_float2(tf32_rna(ob[j][0] * inv0), tf32_rna(ob[j][1] * inv0));
        *(float2*)&d1[j * 8 + lc * 2] =
            make_float2(tf32_rna(ob[j][2] * inv1), tf32_rna(ob[j][3] * inv1));
    }
}

// ---------------------------------------------------------------------------
extern "C" void kernel_launch(void* const* d_in, const int* in_sizes, int n_in,
                              void* d_out, int out_size) {
    const float* x     = (const float*)d_in[0];
    const float* Wqkv  = (const float*)d_in[1];
    const float* bqkv  = (const float*)d_in[2];
    const float* Wproj = (const float*)d_in[3];
    const float* bproj = (const float*)d_in[4];
    float* out = (float*)d_out;

    const int gemm_shm = 2 * STG_F * (int)sizeof(float);        // 41984 B
    const int attn_shm = ATTN_SM_F * (int)sizeof(float);        // 92160 B

    // 0) pre-round x / W_qkv / W_proj to tf32
    pre_round<<<(int)((TOT4 + 255) / 256), 256>>>(x, Wqkv, Wproj);

    // 1) QKV projection (tf32 MMA) -> q (scaled), k [H,SEQ,HD], v [H,HD,SEQ]
    cudaFuncSetAttribute(gemm_tc<3 * DIM, 0>, cudaFuncAttributeMaxDynamicSharedMemorySize, gemm_shm);
    gemm_tc<3 * DIM, 0><<<dim3(24, 32), 256, gemm_shm>>>(bqkv, nullptr);

    // 2) warp-MMA tf32 flash attention (register-resident P)
    cudaFuncSetAttribute(attn_mma, cudaFuncAttributeMaxDynamicSharedMemorySize, attn_shm);
    attn_mma<<<dim3(SEQ / 64, NH), 128, attn_shm>>>();

    // 3) Output projection (tf32 MMA)
    cudaFuncSetAttribute(gemm_tc<DIM, 1>, cudaFuncAttributeMaxDynamicSharedMemorySize, gemm_shm);
    gemm_tc<DIM, 1><<<dim3(8, 32), 256, gemm_shm>>>(bproj, out);
}

// round 9
// speedup vs baseline: 10.0524x; 1.0106x over previous
#include <cuda_runtime.h>
#include <cstdint>

#define SEQ  4096
#define DIM  1024
#define NH   16
#define HD   64

// Scratch (allocation-free rule: __device__ globals)
__device__ float g_q[(size_t)NH * SEQ * HD];   // [H][SEQ][HD] tf32, pre-scaled 0.125
__device__ float g_k[(size_t)NH * SEQ * HD];   // [H][SEQ][HD] tf32
__device__ float g_v[(size_t)NH * HD * SEQ];   // [H][HD][SEQ] tf32 (d-major!)
__device__ float g_att[(size_t)SEQ * DIM];     // tf32 (attn epilogue)
__device__ float g_x [(size_t)SEQ * DIM];
__device__ float g_wq[(size_t)DIM * 3 * DIM];
__device__ float g_wp[(size_t)DIM * DIM];

// ---------------------------------------------------------------------------
__device__ __forceinline__ uint32_t smem_u32(const void* p) {
    uint32_t a;
    asm("{ .reg .u64 t; cvta.to.shared.u64 t, %1; cvt.u32.u64 %0, t; }" : "=r"(a) : "l"(p));
    return a;
}
__device__ __forceinline__ float ex2f(float x) {
    float r; asm("ex2.approx.ftz.f32 %0, %1;" : "=f"(r) : "f"(x)); return r;
}
__device__ __forceinline__ float tf32_rna(float x) {
    uint32_t u; asm("cvt.rna.tf32.f32 %0, %1;" : "=r"(u) : "f"(x)); return __uint_as_float(u);
}
__device__ __forceinline__ void cp16(uint32_t dst, const void* src) {
    asm volatile("cp.async.cg.shared.global [%0], [%1], 16;" :: "r"(dst), "l"(src));
}
#define CP_COMMIT() asm volatile("cp.async.commit_group;" ::: "memory")
#define CP_WAITG1() asm volatile("cp.async.wait_group 1;" ::: "memory")

__device__ __forceinline__ void mma_tf32(float* d, const float* a, float b0, float b1) {
    asm volatile(
        "mma.sync.aligned.m16n8k8.row.col.f32.tf32.tf32.f32 "
        "{%0,%1,%2,%3}, {%4,%5,%6,%7}, {%8,%9}, {%0,%1,%2,%3};"
        : "+f"(d[0]), "+f"(d[1]), "+f"(d[2]), "+f"(d[3])
        : "r"(__float_as_uint(a[0])), "r"(__float_as_uint(a[1])),
          "r"(__float_as_uint(a[2])), "r"(__float_as_uint(a[3])),
          "r"(__float_as_uint(b0)), "r"(__float_as_uint(b1)));
}

#define LOG2E 1.44269504f

// ---------------------------------------------------------------------------
// Pre-round x / W_qkv / W_proj to tf32 (RNA) once per launch.
// ---------------------------------------------------------------------------
#define XN   ((size_t)SEQ * DIM)
#define WQN  ((size_t)DIM * 3 * DIM)
#define WPN  ((size_t)DIM * DIM)
#define TOT4 ((XN + WQN + WPN) / 4)

__global__ __launch_bounds__(256) void pre_round(const float* __restrict__ x,
                                                 const float* __restrict__ wq,
                                                 const float* __restrict__ wp) {
    size_t i = (size_t)blockIdx.x * blockDim.x + threadIdx.x;
    if (i >= TOT4) return;
    const float* src;
    float* dst;
    size_t off;
    if (i < XN / 4)                { src = x;  dst = g_x;  off = i; }
    else if (i < (XN + WQN) / 4)   { src = wq; dst = g_wq; off = i - XN / 4; }
    else                           { src = wp; dst = g_wp; off = i - (XN + WQN) / 4; }
    float4 v = ((const float4*)src)[off];
    v.x = tf32_rna(v.x); v.y = tf32_rna(v.y);
    v.z = tf32_rna(v.z); v.w = tf32_rna(v.w);
    ((float4*)dst)[off] = v;
}

// ---------------------------------------------------------------------------
// tf32 warp-MMA GEMM, 3-stage / single-barrier-per-chunk pipeline.
// ---------------------------------------------------------------------------
#define ASTR 24
#define BSTR 136
#define A_ST_F (128 * ASTR)
#define B_ST_F (16 * BSTR)
#define STG_F  (A_ST_F + B_ST_F)       // 5248 floats / stage
#define NCHUNK (DIM / 16)              // 64

template <int N_, int MODE>
__global__ __launch_bounds__(256) void gemm_tc(const float* __restrict__ bias,
                                               float* __restrict__ C) {
    extern __shared__ float sm[];
    const uint32_t sb = smem_u32(sm);
    const int K = DIM;
    const float* A = (MODE == 1) ? g_att : g_x;
    const float* B = (MODE == 1) ? g_wp : g_wq;

    const int t    = threadIdx.x;
    const int w    = t >> 5;
    const int lane = t & 31;
    const int lr   = lane >> 2;
    const int lc   = lane & 3;
    const int wm   = (w >> 2) * 64;
    const int wn   = (w & 3) * 32;
    const int rowBase = blockIdx.y * 128;
    const int colBase = blockIdx.x * 128;

    auto load_chunk = [&](int k0, int s) {
        uint32_t base = sb + (uint32_t)s * (STG_F * 4);
#pragma unroll
        for (int i = 0; i < 2; i++) {
            int id = t + i * 256;
            int r  = id >> 2;
            int c4 = id & 3;
            cp16(base + (uint32_t)r * (ASTR * 4) + (uint32_t)c4 * 16,
                 A + (size_t)(rowBase + r) * K + k0 + c4 * 4);
        }
#pragma unroll
        for (int i = 0; i < 2; i++) {
            int id = t + i * 256;
            int r  = id >> 5;
            int c4 = id & 31;
            int j  = r & 7;
            int rs = (r & 8) + ((j & 1) ? (j >> 1) + 4 : (j >> 1));
            cp16(base + (uint32_t)(A_ST_F * 4) + (uint32_t)rs * (BSTR * 4) + (uint32_t)c4 * 16,
                 B + (size_t)(k0 + r) * N_ + colBase + c4 * 4);
        }
        CP_COMMIT();
    };

    load_chunk(0, 0);
    load_chunk(16, 1);

    float acc[4][4][4];
#pragma unroll
    for (int mt = 0; mt < 4; mt++)
#pragma unroll
        for (int nt = 0; nt < 4; nt++)
#pragma unroll
            for (int i = 0; i < 4; i++) acc[mt][nt][i] = 0.f;

    for (int kc = 0; kc < NCHUNK; kc++) {
        const int s = kc % 3;
        const float* As = sm + s * STG_F;
        const float* Bs = As + A_ST_F;

        CP_WAITG1();          // chunk kc resident
        __syncthreads();      // all warps past chunk kc-1 (stage (kc+2)%3 free)

        if (kc + 2 < NCHUNK) load_chunk((kc + 2) * 16, (kc + 2) % 3);
        else CP_COMMIT();     // uniform group accounting

#pragma unroll
        for (int kk = 0; kk < 2; kk++) {
            const int k = kk * 8;
            float af[4][4];
#pragma unroll
            for (int mt = 0; mt < 4; mt++) {
                int mb = wm + mt * 16;
                float2 a0 = *(const float2*)&As[(mb + lr) * ASTR + k + 2 * lc];
                float2 a1 = *(const float2*)&As[(mb + lr + 8) * ASTR + k + 2 * lc];
                af[mt][0] = a0.x; af[mt][2] = a0.y;
                af[mt][1] = a1.x; af[mt][3] = a1.y;
            }
            float bf[4][2];
#pragma unroll
            for (int nt = 0; nt < 4; nt++) {
                int n = wn + nt * 8 + lr;
                bf[nt][0] = Bs[(k + lc) * BSTR + n];
                bf[nt][1] = Bs[(k + lc + 4) * BSTR + n];
            }
#pragma unroll
            for (int mt = 0; mt < 4; mt++)
#pragma unroll
                for (int nt = 0; nt < 4; nt++)
                    mma_tf32(acc[mt][nt], af[mt], bf[nt][0], bf[nt][1]);
        }
    }

    // Epilogue
#pragma unroll
    for (int nt = 0; nt < 4; nt++) {
        int c = colBase + wn + nt * 8 + 2 * lc;
        float2 bv = *(const float2*)&bias[c];
#pragma unroll
        for (int mt = 0; mt < 4; mt++) {
            int r0 = rowBase + wm + mt * 16 + lr;
            int r1 = r0 + 8;
            float v00 = acc[mt][nt][0] + bv.x, v01 = acc[mt][nt][1] + bv.y;
            float v10 = acc[mt][nt][2] + bv.x, v11 = acc[mt][nt][3] + bv.y;
            if (MODE == 0) {
                int which = c >> 10;
                int c2    = c & 1023;
                int head  = c2 >> 6;
                int d     = c2 & 63;
                if (which == 0) {
                    float* dq = g_q + ((size_t)head * SEQ) * HD + d;
                    *(float2*)&dq[(size_t)r0 * HD] =
                        make_float2(tf32_rna(v00 * 0.125f), tf32_rna(v01 * 0.125f));
                    *(float2*)&dq[(size_t)r1 * HD] =
                        make_float2(tf32_rna(v10 * 0.125f), tf32_rna(v11 * 0.125f));
                } else if (which == 1) {
                    float* dk = g_k + ((size_t)head * SEQ) * HD + d;
                    *(float2*)&dk[(size_t)r0 * HD] = make_float2(tf32_rna(v00), tf32_rna(v01));
                    *(float2*)&dk[(size_t)r1 * HD] = make_float2(tf32_rna(v10), tf32_rna(v11));
                } else {
                    float* dv = g_v + (size_t)head * HD * SEQ;
                    dv[(size_t)(d)     * SEQ + r0] = tf32_rna(v00);
                    dv[(size_t)(d + 1) * SEQ + r0] = tf32_rna(v01);
                    dv[(size_t)(d)     * SEQ + r1] = tf32_rna(v10);
                    dv[(size_t)(d + 1) * SEQ + r1] = tf32_rna(v11);
                }
            } else {
                *(float2*)&C[(size_t)r0 * N_ + c] = make_float2(v00, v01);
                *(float2*)&C[(size_t)r1 * N_ + c] = make_float2(v10, v11);
            }
        }
    }
}

// ---------------------------------------------------------------------------
// Warp-MMA tf32 flash attention: register-resident P, 3-stage KV pipeline,
// ONE barrier per iteration, copies overlap compute. Q staged through stage-2
// buffer before its first cp.async fill.
// ---------------------------------------------------------------------------
#define PSTR 72
#define STAGE_F (2 * 64 * PSTR)        // 9216 floats (K + V)
#define ATTN_SM_F (3 * STAGE_F)        // 27648 floats = 110592 B

__global__ __launch_bounds__(128, 2) void attn_mma() {
    extern __shared__ float sm[];
    const uint32_t sb = smem_u32(sm);

    const int t    = threadIdx.x;
    const int lane = t & 31;
    const int lr   = lane >> 2;
    const int lc   = lane & 3;
    const int w16  = (t >> 5) * 16;
    const int h  = blockIdx.y;
    const int qt = blockIdx.x;

    const float* Kh = g_k + (size_t)h * SEQ * HD;   // [key][d]
    const float* Vh = g_v + (size_t)h * HD * SEQ;   // [d][key]

    auto load_stage = [&](int kt2, int s) {
#pragma unroll
        for (int i = 0; i < 16; i++) {
            int id   = t + i * 128;            // 0..2047
            int tile = id >> 10;               // 0=K 1=V
            int r    = (id >> 4) & 63;
            int c4   = id & 15;
            uint32_t dst = sb + (uint32_t)s * (STAGE_F * 4)
                              + (uint32_t)tile * (64 * PSTR * 4)
                              + (uint32_t)r * (PSTR * 4) + (uint32_t)c4 * 16;
            const float* src = tile
                ? Vh + (size_t)r * SEQ + (size_t)kt2 * 64 + c4 * 4     // r = d
                : Kh + ((size_t)kt2 * 64 + r) * HD + c4 * 4;           // r = key
            cp16(dst, src);
        }
        CP_COMMIT();
    };

    load_stage(0, 0);
    load_stage(1, 1);

    // Stage Q through the (not yet filled) stage-2 buffer
    float* Qs = sm + 2 * STAGE_F;
    {
        const float* Qg = g_q + ((size_t)h * SEQ + (size_t)qt * 64) * HD;
#pragma unroll
        for (int i = 0; i < 8; i++) {
            int id = t + i * 128;
            int r  = id >> 4;
            int c  = (id & 15) * 4;
            *(float4*)&Qs[r * PSTR + c] = *(const float4*)&Qg[r * HD + c];
        }
    }
    __syncthreads();
    float qf[8][4];
#pragma unroll
    for (int k = 0; k < 8; k++) {
        float2 a0 = *(const float2*)&Qs[(w16 + lr) * PSTR + k * 8 + 2 * lc];
        float2 a1 = *(const float2*)&Qs[(w16 + lr + 8) * PSTR + k * 8 + 2 * lc];
        qf[k][0] = a0.x; qf[k][2] = a0.y;
        qf[k][1] = a1.x; qf[k][3] = a1.y;
    }
    // iter-0's loop-top barrier orders these reads before stage-2's first fill

    float ob[8][4];
#pragma unroll
    for (int j = 0; j < 8; j++)
#pragma unroll
        for (int i = 0; i < 4; i++) ob[j][i] = 0.f;
    float accl[4] = {0.f, 0.f, 0.f, 0.f};
    const float bl = (lr == 0) ? 1.f : 0.f;
    float m0 = -1e30f, m1 = -1e30f;

    for (int kt = 0; kt < SEQ / 64; kt++) {
        const int s = kt % 3;
        const float* Ks = sm + s * STAGE_F;
        const float* Vs = Ks + 64 * PSTR;

        CP_WAITG1();          // tile kt resident
        __syncthreads();      // all warps past iter kt-1 (stage (kt+2)%3 free)

        if (kt + 2 < SEQ / 64) load_stage(kt + 2, (kt + 2) % 3);
        else CP_COMMIT();

        // ---- S = Q * K^T ----
        float sc[8][4];
#pragma unroll
        for (int j = 0; j < 8; j++)
#pragma unroll
            for (int i = 0; i < 4; i++) sc[j][i] = 0.f;
#pragma unroll
        for (int k = 0; k < 8; k++) {
#pragma unroll
            for (int j = 0; j < 8; j++) {
                float2 b = *(const float2*)&Ks[(j * 8 + lr) * PSTR + k * 8 + 2 * lc];
                mma_tf32(sc[j], qf[k], b.x, b.y);
            }
        }

        // ---- online softmax, P stays in registers ----
        float mx0 = sc[0][0], mx1 = sc[0][2];
#pragma unroll
        for (int j = 0; j < 8; j++) {
            mx0 = fmaxf(mx0, fmaxf(sc[j][0], sc[j][1]));
            mx1 = fmaxf(mx1, fmaxf(sc[j][2], sc[j][3]));
        }
        mx0 = fmaxf(mx0, __shfl_xor_sync(0xffffffffu, mx0, 1));
        mx0 = fmaxf(mx0, __shfl_xor_sync(0xffffffffu, mx0, 2));
        mx1 = fmaxf(mx1, __shfl_xor_sync(0xffffffffu, mx1, 1));
        mx1 = fmaxf(mx1, __shfl_xor_sync(0xffffffffu, mx1, 2));
        float nm0 = fmaxf(m0, mx0), nm1 = fmaxf(m1, mx1);
        float corr0 = ex2f((m0 - nm0) * LOG2E);
        float corr1 = ex2f((m1 - nm1) * LOG2E);
#pragma unroll
        for (int j = 0; j < 8; j++) {
            sc[j][0] = ex2f((sc[j][0] - nm0) * LOG2E);
            sc[j][1] = ex2f((sc[j][1] - nm0) * LOG2E);
            sc[j][2] = ex2f((sc[j][2] - nm1) * LOG2E);
            sc[j][3] = ex2f((sc[j][3] - nm1) * LOG2E);
        }
        m0 = nm0; m1 = nm1;
#pragma unroll
        for (int j = 0; j < 8; j++) {
            ob[j][0] *= corr0; ob[j][1] *= corr0;
            ob[j][2] *= corr1; ob[j][3] *= corr1;
        }
        accl[0] *= corr0; accl[2] *= corr1;

        // ---- O += P*V ; l += P*1 ----
#pragma unroll
        for (int k = 0; k < 8; k++) {
            float pf[4];
            pf[0] = sc[k][0];
            pf[1] = sc[k][2];
            pf[2] = sc[k][1];
            pf[3] = sc[k][3];
#pragma unroll
            for (int j = 0; j < 8; j++) {
                float2 b = *(const float2*)&Vs[(j * 8 + lr) * PSTR + k * 8 + 2 * lc];
                mma_tf32(ob[j], pf, b.x, b.y);
            }
            mma_tf32(accl, pf, bl, bl);
        }
        // no post-consume barrier: next iter's loop-top barrier covers reuse
    }

    float l0 = __shfl_sync(0xffffffffu, accl[0], lane & 28);
    float l1 = __shfl_sync(0xffffffffu, accl[2], lane & 28);
    float inv0 = 1.f / l0, inv1 = 1.f / l1;
    float* d0 = g_att + ((size_t)qt * 64 + w16 + lr) * DIM + h * HD;
    float* d1 = d0 + 8 * DIM;
#pragma unroll
    for (int j = 0; j < 8; j++) {
        *(float2*)&d0[j * 8 + lc * 2] =
            make_float2(tf32_rna(ob[j][0] * inv0), tf32_rna(ob[j][1] * inv0));
        *(float2*)&d1[j * 8 + lc * 2] =
            make_float2(tf32_rna(ob[j][2] * inv1), tf32_rna(ob[j][3] * inv1));
    }
}

// ---------------------------------------------------------------------------
extern "C" void kernel_launch(void* const* d_in, const int* in_sizes, int n_in,
                              void* d_out, int out_size) {
    const float* x     = (const float*)d_in[0];
    const float* Wqkv  = (const float*)d_in[1];
    const float* bqkv  = (const float*)d_in[2];
    const float* Wproj = (const float*)d_in[3];
    const float* bproj = (const float*)d_in[4];
    float* out = (float*)d_out;

    const int gemm_shm = 3 * STG_F * (int)sizeof(float);        // 62976 B
    const int attn_shm = ATTN_SM_F * (int)sizeof(float);        // 110592 B

    // 0) pre-round x / W_qkv / W_proj to tf32
    pre_round<<<(int)((TOT4 + 255) / 256), 256>>>(x, Wqkv, Wproj);

    // 1) QKV projection (tf32 MMA, 3-stage pipeline)
    cudaFuncSetAttribute(gemm_tc<3 * DIM, 0>, cudaFuncAttributeMaxDynamicSharedMemorySize, gemm_shm);
    gemm_tc<3 * DIM, 0><<<dim3(24, 32), 256, gemm_shm>>>(bqkv, nullptr);

    // 2) warp-MMA tf32 flash attention (3-stage, 1 barrier/iter)
    cudaFuncSetAttribute(attn_mma, cudaFuncAttributeMaxDynamicSharedMemorySize, attn_shm);
    attn_mma<<<dim3(SEQ / 64, NH), 128, attn_shm>>>();

    // 3) Output projection (tf32 MMA, 3-stage pipeline)
    cudaFuncSetAttribute(gemm_tc<DIM, 1>, cudaFuncAttributeMaxDynamicSharedMemorySize, gemm_shm);
    gemm_tc<DIM, 1><<<dim3(8, 32), 256, gemm_shm>>>(bproj, out);
}